// round 13
// baseline (speedup 1.0000x reference)
#include <cuda_runtime.h>
#include <cuda_fp16.h>
#include <math.h>
#include <stdint.h>

// ---------------- constants (problem shapes are fixed) ----------------
#define B_   4
#define N_   4096
#define D_   256
#define H_   8
#define G_   8
#define DH_  64
#define INNER_ 512
#define M_   1024
#define KS_  6
#define QSCALE 0.1803368801111f   // 0.125 * log2(e)

// ---------------- fp16 mma helper ----------------
__device__ __forceinline__ void mma_f16(float* d,
                                        uint32_t a0, uint32_t a1, uint32_t a2, uint32_t a3,
                                        uint32_t b0, uint32_t b1) {
    asm("mma.sync.aligned.m16n8k16.row.col.f32.f16.f16.f32 "
        "{%0,%1,%2,%3}, {%4,%5,%6,%7}, {%8,%9}, {%0,%1,%2,%3};"
        : "+f"(d[0]), "+f"(d[1]), "+f"(d[2]), "+f"(d[3])
        : "r"(a0), "r"(a1), "r"(a2), "r"(a3), "r"(b0), "r"(b1));
}
__device__ __forceinline__ void ldm_x4(uint32_t& r0, uint32_t& r1, uint32_t& r2, uint32_t& r3,
                                       uint32_t addr) {
    asm volatile("ldmatrix.sync.aligned.m8n8.x4.shared.b16 {%0,%1,%2,%3}, [%4];"
                 : "=r"(r0), "=r"(r1), "=r"(r2), "=r"(r3) : "r"(addr));
}
__device__ __forceinline__ void stm_x4(uint32_t addr, uint32_t r0, uint32_t r1,
                                       uint32_t r2, uint32_t r3) {
    asm volatile("stmatrix.sync.aligned.m8n8.x4.shared.b16 [%0], {%1,%2,%3,%4};"
                 :: "r"(addr), "r"(r0), "r"(r1), "r"(r2), "r"(r3));
}
__device__ __forceinline__ uint32_t pack_h2(float lo, float hi) {
    uint32_t r;
    asm("cvt.rn.f16x2.f32 %0, %1, %2;" : "=r"(r) : "f"(hi), "f"(lo));
    return r;
}
__device__ __forceinline__ uint32_t cvta_smem(const void* p) {
    return (uint32_t)__cvta_generic_to_shared(p);
}
#define CP_A16(dst_u32, src_ptr) \
    asm volatile("cp.async.cg.shared.global [%0], [%1], 16;" :: "r"(dst_u32), "l"(src_ptr))

// ---------------- scratch ----------------
__device__ float  g_q  [B_ * N_ * INNER_];
__device__ __half g_qh [B_ * N_ * INNER_];
__device__ float  g_pos[B_ * G_ * M_];
__device__ __half g_kh [B_ * M_ * INNER_];
__device__ __half g_vth[B_ * H_ * DH_ * M_];
__device__ __half g_aoh[B_ * N_ * INNER_];

// ---------------- K1: q = grouped conv1x1, GEMM-tiled per group ----------------
__global__ __launch_bounds__(256) void k_qproj(const float* __restrict__ x,
                                               const float* __restrict__ px,
                                               const float* __restrict__ wq) {
    __shared__ float sIn[64][68];
    __shared__ float sW [64][68];
    int tok0 = blockIdx.x * 64;
    int g    = blockIdx.y;
    int tid  = threadIdx.x;
    int ty = tid >> 4, tx = tid & 15;

    const float* src = (g < 4) ? px : x;
    int cb = (g & 3) * 64;

#pragma unroll
    for (int it = 0; it < 4; it++) {
        int idx = tid + it * 256;
        int r = idx >> 4, c4 = (idx & 15) * 4;
        *(float4*)&sIn[r][c4] = *(const float4*)&src[(size_t)(tok0 + r) * D_ + cb + c4];
        *(float4*)&sW [r][c4] = *(const float4*)&wq [(size_t)(g * 64 + r) * 64 + c4];
    }
    __syncthreads();

    float acc[4][4];
#pragma unroll
    for (int i = 0; i < 4; i++)
#pragma unroll
        for (int j = 0; j < 4; j++) acc[i][j] = 0.f;

#pragma unroll
    for (int d0 = 0; d0 < 64; d0 += 4) {
        float4 av[4], wv[4];
#pragma unroll
        for (int i = 0; i < 4; i++) av[i] = *(const float4*)&sIn[ty + 16 * i][d0];
#pragma unroll
        for (int j = 0; j < 4; j++) wv[j] = *(const float4*)&sW[tx + 16 * j][d0];
#pragma unroll
        for (int i = 0; i < 4; i++)
#pragma unroll
            for (int j = 0; j < 4; j++) {
                acc[i][j] = fmaf(av[i].x, wv[j].x, acc[i][j]);
                acc[i][j] = fmaf(av[i].y, wv[j].y, acc[i][j]);
                acc[i][j] = fmaf(av[i].z, wv[j].z, acc[i][j]);
                acc[i][j] = fmaf(av[i].w, wv[j].w, acc[i][j]);
            }
    }
#pragma unroll
    for (int i = 0; i < 4; i++)
#pragma unroll
        for (int j = 0; j < 4; j++) {
            size_t o = (size_t)(tok0 + ty + 16 * i) * INNER_ + g * 64 + tx + 16 * j;
            g_q [o] = acc[i][j];
            g_qh[o] = __float2half_rn(acc[i][j] * QSCALE);
        }
}

// ---------------- K2: offsets -> sampling positions ----------------
__global__ __launch_bounds__(256) void k_offsets(const float* __restrict__ w1,
                                                 const float* __restrict__ b1,
                                                 const float* __restrict__ w2) {
    __shared__ float red[8];
    int tid = threadIdx.x;
    int p = blockIdx.x * 4 + (tid >> 6);
    int c = tid & 63;
    int bc = p >> 10, m = p & (M_ - 1);
    int b = bc >> 3, g = bc & 7;
    const float* qbase = g_q + (size_t)b * N_ * INNER_ + g * 64 + c;

    float h = b1[c];
    int n0 = 4 * m - 1;
#pragma unroll
    for (int k = 0; k < KS_; k++) {
        int n = n0 + k;
        if (n >= 0 && n < N_) h = fmaf(qbase[(size_t)n * INNER_], w1[c * KS_ + k], h);
    }
    float ge  = 0.5f * h * (1.f + erff(h * 0.70710678118654752f));
    float val = ge * w2[c];
#pragma unroll
    for (int o = 16; o > 0; o >>= 1) val += __shfl_xor_sync(0xffffffffu, val, o);
    if ((tid & 31) == 0) red[tid >> 5] = val;
    __syncthreads();
    if (tid < 4) {
        float off = tanhf(red[2 * tid] + red[2 * tid + 1]) * 4.0f;
        int pp = blockIdx.x * 4 + tid;
        int mm = pp & (M_ - 1);
        g_pos[pp] = ((float)mm + off) * ((float)N_ / (float)(M_ - 1)) - 0.5f;
    }
}

// ---------------- K3: gather + k/v conv1x1; K fp16, V fp16 transposed ----------------
__global__ __launch_bounds__(256) void k_kv(const float* __restrict__ px,
                                            const float* __restrict__ wk,
                                            const float* __restrict__ wv) {
    __shared__ float skv[32][33];
    __shared__ float sW [128][33];
    int blk = blockIdx.x;
    int bc  = blk >> 5;
    int m0  = (blk & 31) * 32;
    int b = bc >> 3, g = bc & 7;
    int tid = threadIdx.x;

#pragma unroll
    for (int it = 0; it < 16; it++) {
        int idx = tid + it * 256;
        int row = idx >> 5, d = idx & 31;
        const float* w = (row < 64) ? wk : wv;
        sW[row][d] = w[(size_t)(g * 64 + (row & 63)) * 32 + d];
    }

#pragma unroll
    for (int it = 0; it < 4; it++) {
        int idx = tid + it * 256;
        int m = idx & 31, ch = idx >> 5;
        float pos = g_pos[bc * M_ + m0 + m];
        float fp  = floorf(pos);
        int   i0  = (int)fp;
        float w1f = pos - fp;
        const float* base = px + (size_t)b * N_ * D_ + g * 32 + ch;
        float v0 = (i0 >= 0     && i0     < N_) ? base[(size_t)i0 * D_]       : 0.f;
        float v1 = (i0 + 1 >= 0 && i0 + 1 < N_) ? base[(size_t)(i0 + 1) * D_] : 0.f;
        skv[ch][m] = v0 * (1.f - w1f) + v1 * w1f;
    }
    __syncthreads();

#pragma unroll
    for (int u = 0; u < 8; u++) {
        int idx = tid + u * 256;
        int o = idx & 63, msub = idx >> 6;
        float acc = 0.f;
#pragma unroll
        for (int d = 0; d < 32; d++) acc = fmaf(skv[d][msub], sW[o][d], acc);
        g_kh[((size_t)b * M_ + m0 + msub) * INNER_ + g * 64 + o] = __float2half_rn(acc);
    }
#pragma unroll
    for (int u = 0; u < 8; u++) {
        int idx = tid + u * 256;
        int m = idx & 31, o = idx >> 5;
        float acc = 0.f;
#pragma unroll
        for (int d = 0; d < 32; d++) acc = fmaf(skv[d][m], sW[64 + o][d], acc);
        g_vth[((size_t)(b * 8 + g) * 64 + o) * M_ + m0 + m] = __float2half_rn(acc);
    }
}

// ---------------- K4: flash attention, BQ=256, 8 warps, fp16 mma + ldmatrix ----------------
// smem u32 (stride 36): Q[256*36] | K 2x[64*36] | Vt 2x[64*36] | P[256*36]
#define ATTN_SMEM ((256 * 36 + 4 * 64 * 36 + 256 * 36) * 4)
__global__ void __launch_bounds__(256, 2) k_attn() {
    int blk = blockIdx.x;            // b*128 + h*16 + qt   (grid 512)
    int qt = blk & 15;
    int h  = (blk >> 4) & 7;
    int b  = blk >> 7;
    int n0 = qt << 8;

    extern __shared__ uint32_t smem[];
    uint32_t* sQ  = smem;                              // 256*36
    uint32_t* sK  = smem + 256 * 36;                   // 2 x 64*36
    uint32_t* sVt = smem + 256 * 36 + 2 * 64 * 36;     // 2 x 64*36
    uint32_t* sP  = smem + 256 * 36 + 4 * 64 * 36;     // 256*36

    int tid  = threadIdx.x;
    int wid  = tid >> 5, lane = tid & 31;
    int qb   = wid * 32;

    const __half* qsrc   = g_qh  + ((size_t)b * N_ + n0) * INNER_ + h * 64;
    const __half* kbase  = g_kh  + ((size_t)b * M_) * INNER_ + h * 64;
    const __half* vtbase = g_vth + ((size_t)(b * 8 + h) * 64) * M_;

    // ---- stage Q : 256 rows x 8 uint4 = 2048 chunks ----
#pragma unroll
    for (int it = 0; it < 8; it++) {
        int idx = tid + it * 256;
        int rr = idx >> 3, c = idx & 7;
        *(uint4*)&sQ[rr * 36 + c * 4] = *(const uint4*)(qsrc + (size_t)rr * INNER_ + c * 8);
    }

    // ---- ldmatrix/stmatrix lane addresses ----
    int arow = lane & 15;
    int acol = (lane & 16) >> 2;
    int brow = (lane & 7) | ((lane >> 1) & 8);
    int bcol = (lane & 8) >> 1;
    uint32_t aQ  = cvta_smem(sQ)  + (uint32_t)(((qb + arow) * 36 + acol) * 4);
    uint32_t aP  = cvta_smem(sP)  + (uint32_t)(((qb + arow) * 36 + acol) * 4);
    uint32_t stP = aP;
    uint32_t bK  = cvta_smem(sK)  + (uint32_t)((brow * 36 + bcol) * 4);
    uint32_t bV  = cvta_smem(sVt) + (uint32_t)((brow * 36 + bcol) * 4);

    uint32_t sKaddr = cvta_smem(sK);
    uint32_t sVaddr = cvta_smem(sVt);
    auto load_tile = [&](int kt, int buf) {
        int m0 = kt << 6;
#pragma unroll
        for (int it = 0; it < 2; it++) {
            int idx = tid + it * 256;
            int rr = idx >> 3, c = idx & 7;
            CP_A16(sKaddr + (uint32_t)(buf * 64 * 36 + rr * 36 + c * 4) * 4,
                   kbase + (size_t)(m0 + rr) * INNER_ + c * 8);
        }
#pragma unroll
        for (int it = 0; it < 2; it++) {
            int idx = tid + it * 256;
            int rr = idx >> 3, c = idx & 7;
            CP_A16(sVaddr + (uint32_t)(buf * 64 * 36 + rr * 36 + c * 4) * 4,
                   vtbase + (size_t)rr * M_ + m0 + c * 8);
        }
    };

    float out[2][8][4];
#pragma unroll
    for (int u = 0; u < 2; u++)
#pragma unroll
        for (int nt = 0; nt < 8; nt++)
#pragma unroll
            for (int c = 0; c < 4; c++) out[u][nt][c] = 0.f;
    float rmax[2][2], rsum[2][2];
#pragma unroll
    for (int u = 0; u < 2; u++) { rmax[u][0] = rmax[u][1] = -1e30f; rsum[u][0] = rsum[u][1] = 0.f; }

    load_tile(0, 0);
    asm volatile("cp.async.commit_group;");

    for (int kt = 0; kt < 16; kt++) {
        int buf = kt & 1;
        if (kt < 15) {
            load_tile(kt + 1, buf ^ 1);
            asm volatile("cp.async.commit_group;");
            asm volatile("cp.async.wait_group 1;");
        } else {
            asm volatile("cp.async.wait_group 0;");
        }
        __syncthreads();

        uint32_t bufoff = (uint32_t)(buf * 64 * 36 * 4);

        // ---- QK^T ----
        float s[2][8][4];
#pragma unroll
        for (int u = 0; u < 2; u++)
#pragma unroll
            for (int nt = 0; nt < 8; nt++)
#pragma unroll
                for (int c = 0; c < 4; c++) s[u][nt][c] = 0.f;

#pragma unroll
        for (int ks = 0; ks < 4; ks++) {
            uint32_t a[2][4];
            ldm_x4(a[0][0], a[0][1], a[0][2], a[0][3], aQ + ks * 32);
            ldm_x4(a[1][0], a[1][1], a[1][2], a[1][3], aQ + 2304 + ks * 32);
#pragma unroll
            for (int ntp = 0; ntp < 4; ntp++) {
                uint32_t b00, b01, b10, b11;
                ldm_x4(b00, b01, b10, b11, bK + bufoff + ntp * 2304 + ks * 32);
                mma_f16(s[0][2 * ntp    ], a[0][0], a[0][1], a[0][2], a[0][3], b00, b01);
                mma_f16(s[1][2 * ntp    ], a[1][0], a[1][1], a[1][2], a[1][3], b00, b01);
                mma_f16(s[0][2 * ntp + 1], a[0][0], a[0][1], a[0][2], a[0][3], b10, b11);
                mma_f16(s[1][2 * ntp + 1], a[1][0], a[1][1], a[1][2], a[1][3], b10, b11);
            }
        }

        // ---- online softmax (exp2 domain) + P via stmatrix ----
#pragma unroll
        for (int u = 0; u < 2; u++) {
            float lm0 = -1e30f, lm1 = -1e30f;
#pragma unroll
            for (int nt = 0; nt < 8; nt++) {
                lm0 = fmaxf(lm0, fmaxf(s[u][nt][0], s[u][nt][1]));
                lm1 = fmaxf(lm1, fmaxf(s[u][nt][2], s[u][nt][3]));
            }
            lm0 = fmaxf(lm0, __shfl_xor_sync(0xffffffffu, lm0, 1));
            lm0 = fmaxf(lm0, __shfl_xor_sync(0xffffffffu, lm0, 2));
            lm1 = fmaxf(lm1, __shfl_xor_sync(0xffffffffu, lm1, 1));
            lm1 = fmaxf(lm1, __shfl_xor_sync(0xffffffffu, lm1, 2));
            float nm0 = fmaxf(rmax[u][0], lm0), nm1 = fmaxf(rmax[u][1], lm1);
            float f0 = exp2f(rmax[u][0] - nm0), f1 = exp2f(rmax[u][1] - nm1);
            rmax[u][0] = nm0; rmax[u][1] = nm1;
            float ls0 = 0.f, ls1 = 0.f;
#pragma unroll
            for (int ntp = 0; ntp < 4; ntp++) {
                float pa0 = exp2f(s[u][2*ntp][0] - nm0);
                float pa1 = exp2f(s[u][2*ntp][1] - nm0);
                float pa2 = exp2f(s[u][2*ntp][2] - nm1);
                float pa3 = exp2f(s[u][2*ntp][3] - nm1);
                float pb0 = exp2f(s[u][2*ntp+1][0] - nm0);
                float pb1 = exp2f(s[u][2*ntp+1][1] - nm0);
                float pb2 = exp2f(s[u][2*ntp+1][2] - nm1);
                float pb3 = exp2f(s[u][2*ntp+1][3] - nm1);
                ls0 += pa0 + pa1 + pb0 + pb1;
                ls1 += pa2 + pa3 + pb2 + pb3;
                uint32_t q0 = pack_h2(pa0, pa1);
                uint32_t q1 = pack_h2(pa2, pa3);
                uint32_t q2 = pack_h2(pb0, pb1);
                uint32_t q3 = pack_h2(pb2, pb3);
                stm_x4(stP + (uint32_t)(u * 2304 + ntp * 32), q0, q1, q2, q3);
            }
            ls0 += __shfl_xor_sync(0xffffffffu, ls0, 1);
            ls0 += __shfl_xor_sync(0xffffffffu, ls0, 2);
            ls1 += __shfl_xor_sync(0xffffffffu, ls1, 1);
            ls1 += __shfl_xor_sync(0xffffffffu, ls1, 2);
            rsum[u][0] = rsum[u][0] * f0 + ls0;
            rsum[u][1] = rsum[u][1] * f1 + ls1;
#pragma unroll
            for (int nt = 0; nt < 8; nt++) {
                out[u][nt][0] *= f0; out[u][nt][1] *= f0;
                out[u][nt][2] *= f1; out[u][nt][3] *= f1;
            }
        }
        __syncwarp();

        // ---- P @ V ----
#pragma unroll
        for (int ks = 0; ks < 4; ks++) {
            uint32_t a[2][4];
            ldm_x4(a[0][0], a[0][1], a[0][2], a[0][3], aP + ks * 32);
            ldm_x4(a[1][0], a[1][1], a[1][2], a[1][3], aP + 2304 + ks * 32);
#pragma unroll
            for (int ntp = 0; ntp < 4; ntp++) {
                uint32_t b00, b01, b10, b11;
                ldm_x4(b00, b01, b10, b11, bV + bufoff + ntp * 2304 + ks * 32);
                mma_f16(out[0][2 * ntp    ], a[0][0], a[0][1], a[0][2], a[0][3], b00, b01);
                mma_f16(out[1][2 * ntp    ], a[1][0], a[1][1], a[1][2], a[1][3], b00, b01);
                mma_f16(out[0][2 * ntp + 1], a[0][0], a[0][1], a[0][2], a[0][3], b10, b11);
                mma_f16(out[1][2 * ntp + 1], a[1][0], a[1][1], a[1][2], a[1][3], b10, b11);
            }
        }
        __syncthreads();
    }

    // ---- epilogue: fp16 output ----
    int r = lane >> 2, t = lane & 3;
    __half* dsth = g_aoh + ((size_t)b * N_ + n0) * INNER_ + h * 64;
#pragma unroll
    for (int u = 0; u < 2; u++) {
        int rb = qb + u * 16;
        float inv0 = 1.f / rsum[u][0], inv1 = 1.f / rsum[u][1];
#pragma unroll
        for (int nt = 0; nt < 8; nt++) {
            int col = nt * 8 + 2 * t;
            uint32_t p0 = pack_h2(out[u][nt][0] * inv0, out[u][nt][1] * inv0);
            uint32_t p1 = pack_h2(out[u][nt][2] * inv1, out[u][nt][3] * inv1);
            *(uint32_t*)(dsth + (size_t)(rb + r    ) * INNER_ + col) = p0;
            *(uint32_t*)(dsth + (size_t)(rb + r + 8) * INNER_ + col) = p1;
        }
    }
}

// ---------------- K5: output projection, fp16 mma + ldmatrix ----------------
#define OPROJ_SMEM ((128 * 36 + 64 * 36) * 4)
__global__ void __launch_bounds__(256, 3) k_oproj(const float* __restrict__ wo,
                                                  const float* __restrict__ bo,
                                                  float* __restrict__ out) {
    extern __shared__ uint32_t smem[];
    uint32_t* sA = smem;
    uint32_t* sW = smem + 128 * 36;
    int row0 = blockIdx.x * 128;
    int o0   = blockIdx.y * 64;
    int tid  = threadIdx.x;
    int wid  = tid >> 5, lane = tid & 31;
    int r    = lane >> 2, t = lane & 3;
    int qb   = wid * 16;

    int arow = lane & 15;
    int acol = (lane & 16) >> 2;
    int brow = (lane & 7) | ((lane >> 1) & 8);
    int bcol = (lane & 8) >> 1;
    uint32_t aA = cvta_smem(sA) + (uint32_t)(((qb + arow) * 36 + acol) * 4);
    uint32_t bW = cvta_smem(sW) + (uint32_t)((brow * 36 + bcol) * 4);

    float s[8][4];
#pragma unroll
    for (int nt = 0; nt < 8; nt++)
#pragma unroll
        for (int c = 0; c < 4; c++) s[nt][c] = 0.f;

    for (int c0 = 0; c0 < INNER_; c0 += 64) {
#pragma unroll
        for (int it = 0; it < 4; it++) {
            int idx = tid + it * 256;
            int rr = idx >> 3, c = idx & 7;
            *(uint4*)&sA[rr * 36 + c * 4] =
                *(const uint4*)(g_aoh + (size_t)(row0 + rr) * INNER_ + c0 + c * 8);
        }
#pragma unroll
        for (int it = 0; it < 4; it++) {
            int idx = tid + it * 256;
            int rr = idx >> 4, c = idx & 15;
            float4 w4 = *(const float4*)&wo[(size_t)(o0 + rr) * INNER_ + c0 + c * 4];
            sW[rr * 36 + c * 2    ] = pack_h2(w4.x, w4.y);
            sW[rr * 36 + c * 2 + 1] = pack_h2(w4.z, w4.w);
        }
        __syncthreads();
#pragma unroll
        for (int ks = 0; ks < 4; ks++) {
            uint32_t a0, a1, a2, a3;
            ldm_x4(a0, a1, a2, a3, aA + ks * 32);
#pragma unroll
            for (int ntp = 0; ntp < 4; ntp++) {
                uint32_t b00, b01, b10, b11;
                ldm_x4(b00, b01, b10, b11, bW + ntp * 2304 + ks * 32);
                mma_f16(s[2 * ntp    ], a0, a1, a2, a3, b00, b01);
                mma_f16(s[2 * ntp + 1], a0, a1, a2, a3, b10, b11);
            }
        }
        __syncthreads();
    }

#pragma unroll
    for (int nt = 0; nt < 8; nt++) {
        int col = nt * 8 + 2 * t;
        int o = o0 + col;
        float b0 = bo[o], b1 = bo[o + 1];
        *(float2*)&out[(size_t)(row0 + qb + r    ) * D_ + o] =
            make_float2(s[nt][0] + b0, s[nt][1] + b1);
        *(float2*)&out[(size_t)(row0 + qb + r + 8) * D_ + o] =
            make_float2(s[nt][2] + b0, s[nt][3] + b1);
    }
}

// ---------------- launch ----------------
extern "C" void kernel_launch(void* const* d_in, const int* in_sizes, int n_in,
                              void* d_out, int out_size) {
    const float* x      = (const float*)d_in[0];
    const float* prev_x = (const float*)d_in[1];
    const float* wq     = (const float*)d_in[2];
    const float* wk     = (const float*)d_in[3];
    const float* wv     = (const float*)d_in[4];
    const float* wo     = (const float*)d_in[5];
    const float* bo     = (const float*)d_in[6];
    const float* w_off1 = (const float*)d_in[7];
    const float* b_off1 = (const float*)d_in[8];
    const float* w_off2 = (const float*)d_in[9];
    float* out = (float*)d_out;

    cudaFuncSetAttribute(k_attn,  cudaFuncAttributeMaxDynamicSharedMemorySize, ATTN_SMEM);
    cudaFuncSetAttribute(k_oproj, cudaFuncAttributeMaxDynamicSharedMemorySize, OPROJ_SMEM);

    k_qproj  <<<dim3(B_ * N_ / 64, G_), 256>>>(x, prev_x, wq);
    k_offsets<<<(B_ * G_ * M_) / 4, 256>>>(w_off1, b_off1, w_off2);
    k_kv     <<<(B_ * G_ * M_) / 32, 256>>>(prev_x, wk, wv);
    k_attn   <<<B_ * H_ * (N_ / 256), 256, ATTN_SMEM>>>();
    k_oproj  <<<dim3((B_ * N_) / 128, D_ / 64), 256, OPROJ_SMEM>>>(wo, bo, out);
}

// round 14
// speedup vs baseline: 1.2360x; 1.2360x over previous
#include <cuda_runtime.h>
#include <cuda_fp16.h>
#include <math.h>
#include <stdint.h>

// ---------------- constants (problem shapes are fixed) ----------------
#define B_   4
#define N_   4096
#define D_   256
#define H_   8
#define G_   8
#define DH_  64
#define INNER_ 512
#define M_   1024
#define KS_  6
#define QSCALE 0.1803368801111f   // 0.125 * log2(e)

// ---------------- fp16 mma helper ----------------
__device__ __forceinline__ void mma_f16(float* d,
                                        uint32_t a0, uint32_t a1, uint32_t a2, uint32_t a3,
                                        uint32_t b0, uint32_t b1) {
    asm("mma.sync.aligned.m16n8k16.row.col.f32.f16.f16.f32 "
        "{%0,%1,%2,%3}, {%4,%5,%6,%7}, {%8,%9}, {%0,%1,%2,%3};"
        : "+f"(d[0]), "+f"(d[1]), "+f"(d[2]), "+f"(d[3])
        : "r"(a0), "r"(a1), "r"(a2), "r"(a3), "r"(b0), "r"(b1));
}
__device__ __forceinline__ void ldm_x4(uint32_t& r0, uint32_t& r1, uint32_t& r2, uint32_t& r3,
                                       uint32_t addr) {
    asm volatile("ldmatrix.sync.aligned.m8n8.x4.shared.b16 {%0,%1,%2,%3}, [%4];"
                 : "=r"(r0), "=r"(r1), "=r"(r2), "=r"(r3) : "r"(addr));
}
__device__ __forceinline__ void stm_x4(uint32_t addr, uint32_t r0, uint32_t r1,
                                       uint32_t r2, uint32_t r3) {
    asm volatile("stmatrix.sync.aligned.m8n8.x4.shared.b16 [%0], {%1,%2,%3,%4};"
                 :: "r"(addr), "r"(r0), "r"(r1), "r"(r2), "r"(r3));
}
__device__ __forceinline__ uint32_t pack_h2(float lo, float hi) {
    uint32_t r;
    asm("cvt.rn.f16x2.f32 %0, %1, %2;" : "=r"(r) : "f"(hi), "f"(lo));
    return r;
}
__device__ __forceinline__ uint32_t cvta_smem(const void* p) {
    return (uint32_t)__cvta_generic_to_shared(p);
}
#define CP_A16(dst_u32, src_ptr) \
    asm volatile("cp.async.cg.shared.global [%0], [%1], 16;" :: "r"(dst_u32), "l"(src_ptr))

// ---------------- scratch ----------------
__device__ float  g_q  [B_ * N_ * INNER_];
__device__ __half g_qh [B_ * N_ * INNER_];
__device__ __half g_kh [B_ * M_ * INNER_];
__device__ __half g_vth[B_ * H_ * DH_ * M_];
__device__ __half g_aoh[B_ * N_ * INNER_];

// ---------------- K1: q = grouped conv1x1, GEMM-tiled per group ----------------
__global__ __launch_bounds__(256) void k_qproj(const float* __restrict__ x,
                                               const float* __restrict__ px,
                                               const float* __restrict__ wq) {
    __shared__ float sIn[64][68];
    __shared__ float sW [64][68];
    int tok0 = blockIdx.x * 64;
    int g    = blockIdx.y;
    int tid  = threadIdx.x;
    int ty = tid >> 4, tx = tid & 15;

    const float* src = (g < 4) ? px : x;
    int cb = (g & 3) * 64;

#pragma unroll
    for (int it = 0; it < 4; it++) {
        int idx = tid + it * 256;
        int r = idx >> 4, c4 = (idx & 15) * 4;
        *(float4*)&sIn[r][c4] = *(const float4*)&src[(size_t)(tok0 + r) * D_ + cb + c4];
        *(float4*)&sW [r][c4] = *(const float4*)&wq [(size_t)(g * 64 + r) * 64 + c4];
    }
    __syncthreads();

    float acc[4][4];
#pragma unroll
    for (int i = 0; i < 4; i++)
#pragma unroll
        for (int j = 0; j < 4; j++) acc[i][j] = 0.f;

#pragma unroll
    for (int d0 = 0; d0 < 64; d0 += 4) {
        float4 av[4], wv[4];
#pragma unroll
        for (int i = 0; i < 4; i++) av[i] = *(const float4*)&sIn[ty + 16 * i][d0];
#pragma unroll
        for (int j = 0; j < 4; j++) wv[j] = *(const float4*)&sW[tx + 16 * j][d0];
#pragma unroll
        for (int i = 0; i < 4; i++)
#pragma unroll
            for (int j = 0; j < 4; j++) {
                acc[i][j] = fmaf(av[i].x, wv[j].x, acc[i][j]);
                acc[i][j] = fmaf(av[i].y, wv[j].y, acc[i][j]);
                acc[i][j] = fmaf(av[i].z, wv[j].z, acc[i][j]);
                acc[i][j] = fmaf(av[i].w, wv[j].w, acc[i][j]);
            }
    }
#pragma unroll
    for (int i = 0; i < 4; i++)
#pragma unroll
        for (int j = 0; j < 4; j++) {
            size_t o = (size_t)(tok0 + ty + 16 * i) * INNER_ + g * 64 + tx + 16 * j;
            g_q [o] = acc[i][j];
            g_qh[o] = __float2half_rn(acc[i][j] * QSCALE);
        }
}

// ---------------- K2: fused offsets + gather + k/v conv1x1 ----------------
// one block per (b,g, 32 m's); dynamic smem: sQ[130][65] | sW[128][33] | skv[32][33] | sPos[32]
#define OFFKV_SMEM ((130 * 65 + 128 * 33 + 32 * 33 + 32) * 4)
__global__ __launch_bounds__(256) void k_offkv(const float* __restrict__ px,
                                               const float* __restrict__ wk,
                                               const float* __restrict__ wv,
                                               const float* __restrict__ w1,
                                               const float* __restrict__ b1,
                                               const float* __restrict__ w2) {
    extern __shared__ float sm[];
    float (*sQ) [65] = (float(*)[65])sm;                    // 130 q rows of this group
    float (*sW) [33] = (float(*)[33])(sm + 130 * 65);       // wk rows 0..63, wv rows 64..127
    float (*skv)[33] = (float(*)[33])(sm + 130 * 65 + 128 * 33);
    float* sPos      = sm + 130 * 65 + 128 * 33 + 32 * 33;

    int blk = blockIdx.x;               // B*G*(M/32) = 1024 blocks
    int bc  = blk >> 5;
    int m0  = (blk & 31) * 32;
    int b = bc >> 3, g = bc & 7;
    int tid = threadIdx.x;

    // stage group weights
#pragma unroll
    for (int it = 0; it < 16; it++) {
        int idx = tid + it * 256;
        int row = idx >> 5, d = idx & 31;
        const float* w = (row < 64) ? wk : wv;
        sW[row][d] = w[(size_t)(g * 64 + (row & 63)) * 32 + d];
    }
    // stage q rows 4*m0-1 .. 4*m0+128 (130 rows x 64 ch)
    {
        const float* qb = g_q + (size_t)b * N_ * INNER_ + g * 64;
#pragma unroll
        for (int it = 0; it < 33; it++) {
            int idx = tid + it * 256;
            if (idx < 130 * 64) {
                int i = idx >> 6, ch = idx & 63;
                int gr = 4 * m0 - 1 + i;
                sQ[i][ch] = (gr >= 0 && gr < N_) ? qb[(size_t)gr * INNER_ + ch] : 0.f;
            }
        }
    }
    __syncthreads();

    // ---- offsets: 8 threads per position, 8 channels per thread ----
    {
        int p  = tid >> 3;          // 0..31
        int cg = tid & 7;
        float val = 0.f;
#pragma unroll
        for (int j = 0; j < 8; j++) {
            int c = cg * 8 + j;
            float h = b1[c];
#pragma unroll
            for (int k = 0; k < KS_; k++)
                h = fmaf(sQ[4 * p + k][c], w1[c * KS_ + k], h);
            float ge = 0.5f * h * (1.f + erff(h * 0.70710678118654752f));
            val = fmaf(ge, w2[c], val);
        }
        val += __shfl_xor_sync(0xffffffffu, val, 1);
        val += __shfl_xor_sync(0xffffffffu, val, 2);
        val += __shfl_xor_sync(0xffffffffu, val, 4);
        if (cg == 0) {
            float off = tanhf(val) * 4.0f;
            sPos[p] = ((float)(m0 + p) + off) * ((float)N_ / (float)(M_ - 1)) - 0.5f;
        }
    }
    __syncthreads();

    // ---- bilinear gather ----
#pragma unroll
    for (int it = 0; it < 4; it++) {
        int idx = tid + it * 256;
        int m = idx & 31, ch = idx >> 5;
        float pos = sPos[m];
        float fp  = floorf(pos);
        int   i0  = (int)fp;
        float w1f = pos - fp;
        const float* base = px + (size_t)b * N_ * D_ + g * 32 + ch;
        float v0 = (i0 >= 0     && i0     < N_) ? base[(size_t)i0 * D_]       : 0.f;
        float v1 = (i0 + 1 >= 0 && i0 + 1 < N_) ? base[(size_t)(i0 + 1) * D_] : 0.f;
        skv[ch][m] = v0 * (1.f - w1f) + v1 * w1f;
    }
    __syncthreads();

    // ---- K pass (coalesced half writes over o) ----
#pragma unroll
    for (int u = 0; u < 8; u++) {
        int idx = tid + u * 256;
        int o = idx & 63, msub = idx >> 6;
        float acc = 0.f;
#pragma unroll
        for (int d = 0; d < 32; d++) acc = fmaf(skv[d][msub], sW[o][d], acc);
        g_kh[((size_t)b * M_ + m0 + msub) * INNER_ + g * 64 + o] = __float2half_rn(acc);
    }
    // ---- V pass (transposed, coalesced over m) ----
#pragma unroll
    for (int u = 0; u < 8; u++) {
        int idx = tid + u * 256;
        int m = idx & 31, o = idx >> 5;
        float acc = 0.f;
#pragma unroll
        for (int d = 0; d < 32; d++) acc = fmaf(skv[d][m], sW[64 + o][d], acc);
        g_vth[((size_t)(b * 8 + g) * 64 + o) * M_ + m0 + m] = __float2half_rn(acc);
    }
}

// ---------------- K4: flash attention (R12 config: BQ=128, 4 warps, 3 CTAs) ----------------
// smem u32 (stride 36): Q[128*36] | K 2x[64*36] | Vt 2x[64*36] | P[128*36]
#define ATTN_SMEM ((128 * 36 + 4 * 64 * 36 + 128 * 36) * 4)
__global__ void __launch_bounds__(128, 3) k_attn() {
    int blk = blockIdx.x;            // b*256 + h*32 + qt
    int qt = blk & 31;
    int h  = (blk >> 5) & 7;
    int b  = blk >> 8;
    int n0 = qt << 7;

    extern __shared__ uint32_t smem[];
    uint32_t* sQ  = smem;
    uint32_t* sK  = smem + 128 * 36;
    uint32_t* sVt = smem + 128 * 36 + 2 * 64 * 36;
    uint32_t* sP  = smem + 128 * 36 + 4 * 64 * 36;

    int tid  = threadIdx.x;
    int wid  = tid >> 5, lane = tid & 31;
    int qb   = wid * 32;

    const __half* qsrc   = g_qh  + ((size_t)b * N_ + n0) * INNER_ + h * 64;
    const __half* kbase  = g_kh  + ((size_t)b * M_) * INNER_ + h * 64;
    const __half* vtbase = g_vth + ((size_t)(b * 8 + h) * 64) * M_;

#pragma unroll
    for (int it = 0; it < 8; it++) {
        int idx = tid + it * 128;
        int rr = idx >> 3, c = idx & 7;
        *(uint4*)&sQ[rr * 36 + c * 4] = *(const uint4*)(qsrc + (size_t)rr * INNER_ + c * 8);
    }

    int arow = lane & 15;
    int acol = (lane & 16) >> 2;
    int brow = (lane & 7) | ((lane >> 1) & 8);
    int bcol = (lane & 8) >> 1;
    uint32_t aQ  = cvta_smem(sQ)  + (uint32_t)(((qb + arow) * 36 + acol) * 4);
    uint32_t aP  = cvta_smem(sP)  + (uint32_t)(((qb + arow) * 36 + acol) * 4);
    uint32_t stP = aP;
    uint32_t bK  = cvta_smem(sK)  + (uint32_t)((brow * 36 + bcol) * 4);
    uint32_t bV  = cvta_smem(sVt) + (uint32_t)((brow * 36 + bcol) * 4);

    uint32_t sKaddr = cvta_smem(sK);
    uint32_t sVaddr = cvta_smem(sVt);
    auto load_tile = [&](int kt, int buf) {
        int m0 = kt << 6;
#pragma unroll
        for (int it = 0; it < 4; it++) {
            int idx = tid + it * 128;
            int rr = idx >> 3, c = idx & 7;
            CP_A16(sKaddr + (uint32_t)(buf * 64 * 36 + rr * 36 + c * 4) * 4,
                   kbase + (size_t)(m0 + rr) * INNER_ + c * 8);
        }
#pragma unroll
        for (int it = 0; it < 4; it++) {
            int idx = tid + it * 128;
            int rr = idx >> 3, c = idx & 7;
            CP_A16(sVaddr + (uint32_t)(buf * 64 * 36 + rr * 36 + c * 4) * 4,
                   vtbase + (size_t)rr * M_ + m0 + c * 8);
        }
    };

    float out[2][8][4];
#pragma unroll
    for (int u = 0; u < 2; u++)
#pragma unroll
        for (int nt = 0; nt < 8; nt++)
#pragma unroll
            for (int c = 0; c < 4; c++) out[u][nt][c] = 0.f;
    float rmax[2][2], rsum[2][2];
#pragma unroll
    for (int u = 0; u < 2; u++) { rmax[u][0] = rmax[u][1] = -1e30f; rsum[u][0] = rsum[u][1] = 0.f; }

    load_tile(0, 0);
    asm volatile("cp.async.commit_group;");

    for (int kt = 0; kt < 16; kt++) {
        int buf = kt & 1;
        if (kt < 15) {
            load_tile(kt + 1, buf ^ 1);
            asm volatile("cp.async.commit_group;");
            asm volatile("cp.async.wait_group 1;");
        } else {
            asm volatile("cp.async.wait_group 0;");
        }
        __syncthreads();

        uint32_t bufoff = (uint32_t)(buf * 64 * 36 * 4);

        float s[2][8][4];
#pragma unroll
        for (int u = 0; u < 2; u++)
#pragma unroll
            for (int nt = 0; nt < 8; nt++)
#pragma unroll
                for (int c = 0; c < 4; c++) s[u][nt][c] = 0.f;

#pragma unroll
        for (int ks = 0; ks < 4; ks++) {
            uint32_t a[2][4];
            ldm_x4(a[0][0], a[0][1], a[0][2], a[0][3], aQ + ks * 32);
            ldm_x4(a[1][0], a[1][1], a[1][2], a[1][3], aQ + 2304 + ks * 32);
#pragma unroll
            for (int ntp = 0; ntp < 4; ntp++) {
                uint32_t b00, b01, b10, b11;
                ldm_x4(b00, b01, b10, b11, bK + bufoff + ntp * 2304 + ks * 32);
                mma_f16(s[0][2 * ntp    ], a[0][0], a[0][1], a[0][2], a[0][3], b00, b01);
                mma_f16(s[1][2 * ntp    ], a[1][0], a[1][1], a[1][2], a[1][3], b00, b01);
                mma_f16(s[0][2 * ntp + 1], a[0][0], a[0][1], a[0][2], a[0][3], b10, b11);
                mma_f16(s[1][2 * ntp + 1], a[1][0], a[1][1], a[1][2], a[1][3], b10, b11);
            }
        }

#pragma unroll
        for (int u = 0; u < 2; u++) {
            float lm0 = -1e30f, lm1 = -1e30f;
#pragma unroll
            for (int nt = 0; nt < 8; nt++) {
                lm0 = fmaxf(lm0, fmaxf(s[u][nt][0], s[u][nt][1]));
                lm1 = fmaxf(lm1, fmaxf(s[u][nt][2], s[u][nt][3]));
            }
            lm0 = fmaxf(lm0, __shfl_xor_sync(0xffffffffu, lm0, 1));
            lm0 = fmaxf(lm0, __shfl_xor_sync(0xffffffffu, lm0, 2));
            lm1 = fmaxf(lm1, __shfl_xor_sync(0xffffffffu, lm1, 1));
            lm1 = fmaxf(lm1, __shfl_xor_sync(0xffffffffu, lm1, 2));
            float nm0 = fmaxf(rmax[u][0], lm0), nm1 = fmaxf(rmax[u][1], lm1);
            float f0 = exp2f(rmax[u][0] - nm0), f1 = exp2f(rmax[u][1] - nm1);
            rmax[u][0] = nm0; rmax[u][1] = nm1;
            float ls0 = 0.f, ls1 = 0.f;
#pragma unroll
            for (int ntp = 0; ntp < 4; ntp++) {
                float pa0 = exp2f(s[u][2*ntp][0] - nm0);
                float pa1 = exp2f(s[u][2*ntp][1] - nm0);
                float pa2 = exp2f(s[u][2*ntp][2] - nm1);
                float pa3 = exp2f(s[u][2*ntp][3] - nm1);
                float pb0 = exp2f(s[u][2*ntp+1][0] - nm0);
                float pb1 = exp2f(s[u][2*ntp+1][1] - nm0);
                float pb2 = exp2f(s[u][2*ntp+1][2] - nm1);
                float pb3 = exp2f(s[u][2*ntp+1][3] - nm1);
                ls0 += pa0 + pa1 + pb0 + pb1;
                ls1 += pa2 + pa3 + pb2 + pb3;
                uint32_t q0 = pack_h2(pa0, pa1);
                uint32_t q1 = pack_h2(pa2, pa3);
                uint32_t q2 = pack_h2(pb0, pb1);
                uint32_t q3 = pack_h2(pb2, pb3);
                stm_x4(stP + (uint32_t)(u * 2304 + ntp * 32), q0, q1, q2, q3);
            }
            ls0 += __shfl_xor_sync(0xffffffffu, ls0, 1);
            ls0 += __shfl_xor_sync(0xffffffffu, ls0, 2);
            ls1 += __shfl_xor_sync(0xffffffffu, ls1, 1);
            ls1 += __shfl_xor_sync(0xffffffffu, ls1, 2);
            rsum[u][0] = rsum[u][0] * f0 + ls0;
            rsum[u][1] = rsum[u][1] * f1 + ls1;
#pragma unroll
            for (int nt = 0; nt < 8; nt++) {
                out[u][nt][0] *= f0; out[u][nt][1] *= f0;
                out[u][nt][2] *= f1; out[u][nt][3] *= f1;
            }
        }
        __syncwarp();

#pragma unroll
        for (int ks = 0; ks < 4; ks++) {
            uint32_t a[2][4];
            ldm_x4(a[0][0], a[0][1], a[0][2], a[0][3], aP + ks * 32);
            ldm_x4(a[1][0], a[1][1], a[1][2], a[1][3], aP + 2304 + ks * 32);
#pragma unroll
            for (int ntp = 0; ntp < 4; ntp++) {
                uint32_t b00, b01, b10, b11;
                ldm_x4(b00, b01, b10, b11, bV + bufoff + ntp * 2304 + ks * 32);
                mma_f16(out[0][2 * ntp    ], a[0][0], a[0][1], a[0][2], a[0][3], b00, b01);
                mma_f16(out[1][2 * ntp    ], a[1][0], a[1][1], a[1][2], a[1][3], b00, b01);
                mma_f16(out[0][2 * ntp + 1], a[0][0], a[0][1], a[0][2], a[0][3], b10, b11);
                mma_f16(out[1][2 * ntp + 1], a[1][0], a[1][1], a[1][2], a[1][3], b10, b11);
            }
        }
        __syncthreads();
    }

    int r = lane >> 2, t = lane & 3;
    __half* dsth = g_aoh + ((size_t)b * N_ + n0) * INNER_ + h * 64;
#pragma unroll
    for (int u = 0; u < 2; u++) {
        int rb = qb + u * 16;
        float inv0 = 1.f / rsum[u][0], inv1 = 1.f / rsum[u][1];
#pragma unroll
        for (int nt = 0; nt < 8; nt++) {
            int col = nt * 8 + 2 * t;
            uint32_t p0 = pack_h2(out[u][nt][0] * inv0, out[u][nt][1] * inv0);
            uint32_t p1 = pack_h2(out[u][nt][2] * inv1, out[u][nt][3] * inv1);
            *(uint32_t*)(dsth + (size_t)(rb + r    ) * INNER_ + col) = p0;
            *(uint32_t*)(dsth + (size_t)(rb + r + 8) * INNER_ + col) = p1;
        }
    }
}

// ---------------- K5: output projection, fp16 mma + ldmatrix ----------------
#define OPROJ_SMEM ((128 * 36 + 64 * 36) * 4)
__global__ void __launch_bounds__(256, 3) k_oproj(const float* __restrict__ wo,
                                                  const float* __restrict__ bo,
                                                  float* __restrict__ out) {
    extern __shared__ uint32_t smem[];
    uint32_t* sA = smem;
    uint32_t* sW = smem + 128 * 36;
    int row0 = blockIdx.x * 128;
    int o0   = blockIdx.y * 64;
    int tid  = threadIdx.x;
    int wid  = tid >> 5, lane = tid & 31;
    int r    = lane >> 2, t = lane & 3;
    int qb   = wid * 16;

    int arow = lane & 15;
    int acol = (lane & 16) >> 2;
    int brow = (lane & 7) | ((lane >> 1) & 8);
    int bcol = (lane & 8) >> 1;
    uint32_t aA = cvta_smem(sA) + (uint32_t)(((qb + arow) * 36 + acol) * 4);
    uint32_t bW = cvta_smem(sW) + (uint32_t)((brow * 36 + bcol) * 4);

    float s[8][4];
#pragma unroll
    for (int nt = 0; nt < 8; nt++)
#pragma unroll
        for (int c = 0; c < 4; c++) s[nt][c] = 0.f;

    for (int c0 = 0; c0 < INNER_; c0 += 64) {
#pragma unroll
        for (int it = 0; it < 4; it++) {
            int idx = tid + it * 256;
            int rr = idx >> 3, c = idx & 7;
            *(uint4*)&sA[rr * 36 + c * 4] =
                *(const uint4*)(g_aoh + (size_t)(row0 + rr) * INNER_ + c0 + c * 8);
        }
#pragma unroll
        for (int it = 0; it < 4; it++) {
            int idx = tid + it * 256;
            int rr = idx >> 4, c = idx & 15;
            float4 w4 = *(const float4*)&wo[(size_t)(o0 + rr) * INNER_ + c0 + c * 4];
            sW[rr * 36 + c * 2    ] = pack_h2(w4.x, w4.y);
            sW[rr * 36 + c * 2 + 1] = pack_h2(w4.z, w4.w);
        }
        __syncthreads();
#pragma unroll
        for (int ks = 0; ks < 4; ks++) {
            uint32_t a0, a1, a2, a3;
            ldm_x4(a0, a1, a2, a3, aA + ks * 32);
#pragma unroll
            for (int ntp = 0; ntp < 4; ntp++) {
                uint32_t b00, b01, b10, b11;
                ldm_x4(b00, b01, b10, b11, bW + ntp * 2304 + ks * 32);
                mma_f16(s[2 * ntp    ], a0, a1, a2, a3, b00, b01);
                mma_f16(s[2 * ntp + 1], a0, a1, a2, a3, b10, b11);
            }
        }
        __syncthreads();
    }

#pragma unroll
    for (int nt = 0; nt < 8; nt++) {
        int col = nt * 8 + 2 * t;
        int o = o0 + col;
        float b0 = bo[o], b1 = bo[o + 1];
        *(float2*)&out[(size_t)(row0 + qb + r    ) * D_ + o] =
            make_float2(s[nt][0] + b0, s[nt][1] + b1);
        *(float2*)&out[(size_t)(row0 + qb + r + 8) * D_ + o] =
            make_float2(s[nt][2] + b0, s[nt][3] + b1);
    }
}

// ---------------- launch ----------------
extern "C" void kernel_launch(void* const* d_in, const int* in_sizes, int n_in,
                              void* d_out, int out_size) {
    const float* x      = (const float*)d_in[0];
    const float* prev_x = (const float*)d_in[1];
    const float* wq     = (const float*)d_in[2];
    const float* wk     = (const float*)d_in[3];
    const float* wv     = (const float*)d_in[4];
    const float* wo     = (const float*)d_in[5];
    const float* bo     = (const float*)d_in[6];
    const float* w_off1 = (const float*)d_in[7];
    const float* b_off1 = (const float*)d_in[8];
    const float* w_off2 = (const float*)d_in[9];
    float* out = (float*)d_out;

    cudaFuncSetAttribute(k_attn,  cudaFuncAttributeMaxDynamicSharedMemorySize, ATTN_SMEM);
    cudaFuncSetAttribute(k_oproj, cudaFuncAttributeMaxDynamicSharedMemorySize, OPROJ_SMEM);
    cudaFuncSetAttribute(k_offkv, cudaFuncAttributeMaxDynamicSharedMemorySize, OFFKV_SMEM);

    k_qproj <<<dim3(B_ * N_ / 64, G_), 256>>>(x, prev_x, wq);
    k_offkv <<<(B_ * G_ * M_) / 32, 256, OFFKV_SMEM>>>(prev_x, wk, wv, w_off1, b_off1, w_off2);
    k_attn  <<<B_ * H_ * (N_ / 128), 128, ATTN_SMEM>>>();
    k_oproj <<<dim3((B_ * N_) / 128, D_ / 64), 256, OPROJ_SMEM>>>(wo, bo, out);
}

// round 16
// speedup vs baseline: 1.2476x; 1.0094x over previous
#include <cuda_runtime.h>
#include <cuda_fp16.h>
#include <math.h>
#include <stdint.h>

// ---------------- constants (problem shapes are fixed) ----------------
#define B_   4
#define N_   4096
#define D_   256
#define H_   8
#define G_   8
#define DH_  64
#define INNER_ 512
#define M_   1024
#define KS_  6
#define QSCALE 0.1803368801111f   // 0.125 * log2(e)

// ---------------- fp16 mma helper ----------------
__device__ __forceinline__ void mma_f16(float* d,
                                        uint32_t a0, uint32_t a1, uint32_t a2, uint32_t a3,
                                        uint32_t b0, uint32_t b1) {
    asm("mma.sync.aligned.m16n8k16.row.col.f32.f16.f16.f32 "
        "{%0,%1,%2,%3}, {%4,%5,%6,%7}, {%8,%9}, {%0,%1,%2,%3};"
        : "+f"(d[0]), "+f"(d[1]), "+f"(d[2]), "+f"(d[3])
        : "r"(a0), "r"(a1), "r"(a2), "r"(a3), "r"(b0), "r"(b1));
}
__device__ __forceinline__ void ldm_x4(uint32_t& r0, uint32_t& r1, uint32_t& r2, uint32_t& r3,
                                       uint32_t addr) {
    asm volatile("ldmatrix.sync.aligned.m8n8.x4.shared.b16 {%0,%1,%2,%3}, [%4];"
                 : "=r"(r0), "=r"(r1), "=r"(r2), "=r"(r3) : "r"(addr));
}
__device__ __forceinline__ void stm_x4(uint32_t addr, uint32_t r0, uint32_t r1,
                                       uint32_t r2, uint32_t r3) {
    asm volatile("stmatrix.sync.aligned.m8n8.x4.shared.b16 [%0], {%1,%2,%3,%4};"
                 :: "r"(addr), "r"(r0), "r"(r1), "r"(r2), "r"(r3));
}
__device__ __forceinline__ uint32_t pack_h2(float lo, float hi) {
    uint32_t r;
    asm("cvt.rn.f16x2.f32 %0, %1, %2;" : "=r"(r) : "f"(hi), "f"(lo));
    return r;
}
__device__ __forceinline__ uint32_t cvta_smem(const void* p) {
    return (uint32_t)__cvta_generic_to_shared(p);
}
#define CP_A16(dst_u32, src_ptr) \
    asm volatile("cp.async.cg.shared.global [%0], [%1], 16;" :: "r"(dst_u32), "l"(src_ptr))

// ---------------- scratch ----------------
__device__ float  g_q  [B_ * N_ * INNER_];
__device__ __half g_qh [B_ * N_ * INNER_];
__device__ __half g_kh [B_ * M_ * INNER_];
__device__ __half g_vth[B_ * H_ * DH_ * M_];
__device__ __half g_aoh[B_ * N_ * INNER_];

// ---------------- K1: q = grouped conv1x1 (fp32, precision-critical) ----------------
__global__ __launch_bounds__(256) void k_qproj(const float* __restrict__ x,
                                               const float* __restrict__ px,
                                               const float* __restrict__ wq) {
    __shared__ float sIn[64][68];
    __shared__ float sW [64][68];
    int tok0 = blockIdx.x * 64;
    int g    = blockIdx.y;
    int tid  = threadIdx.x;
    int ty = tid >> 4, tx = tid & 15;

    const float* src = (g < 4) ? px : x;
    int cb = (g & 3) * 64;

#pragma unroll
    for (int it = 0; it < 4; it++) {
        int idx = tid + it * 256;
        int r = idx >> 4, c4 = (idx & 15) * 4;
        *(float4*)&sIn[r][c4] = *(const float4*)&src[(size_t)(tok0 + r) * D_ + cb + c4];
        *(float4*)&sW [r][c4] = *(const float4*)&wq [(size_t)(g * 64 + r) * 64 + c4];
    }
    __syncthreads();

    float acc[4][4];
#pragma unroll
    for (int i = 0; i < 4; i++)
#pragma unroll
        for (int j = 0; j < 4; j++) acc[i][j] = 0.f;

#pragma unroll
    for (int d0 = 0; d0 < 64; d0 += 4) {
        float4 av[4], wv[4];
#pragma unroll
        for (int i = 0; i < 4; i++) av[i] = *(const float4*)&sIn[ty + 16 * i][d0];
#pragma unroll
        for (int j = 0; j < 4; j++) wv[j] = *(const float4*)&sW[tx + 16 * j][d0];
#pragma unroll
        for (int i = 0; i < 4; i++)
#pragma unroll
            for (int j = 0; j < 4; j++) {
                acc[i][j] = fmaf(av[i].x, wv[j].x, acc[i][j]);
                acc[i][j] = fmaf(av[i].y, wv[j].y, acc[i][j]);
                acc[i][j] = fmaf(av[i].z, wv[j].z, acc[i][j]);
                acc[i][j] = fmaf(av[i].w, wv[j].w, acc[i][j]);
            }
    }
#pragma unroll
    for (int i = 0; i < 4; i++)
#pragma unroll
        for (int j = 0; j < 4; j++) {
            size_t o = (size_t)(tok0 + ty + 16 * i) * INNER_ + g * 64 + tx + 16 * j;
            g_q [o] = acc[i][j];
            g_qh[o] = __float2half_rn(acc[i][j] * QSCALE);
        }
}

// ---------------- K2: fused offsets + gather + k/v conv1x1 ----------------
#define OFFKV_SMEM ((130 * 65 + 128 * 33 + 32 * 33 + 32) * 4)
__global__ __launch_bounds__(256) void k_offkv(const float* __restrict__ px,
                                               const float* __restrict__ wk,
                                               const float* __restrict__ wv,
                                               const float* __restrict__ w1,
                                               const float* __restrict__ b1,
                                               const float* __restrict__ w2) {
    extern __shared__ float sm[];
    float (*sQ) [65] = (float(*)[65])sm;
    float (*sW) [33] = (float(*)[33])(sm + 130 * 65);
    float (*skv)[33] = (float(*)[33])(sm + 130 * 65 + 128 * 33);
    float* sPos      = sm + 130 * 65 + 128 * 33 + 32 * 33;

    int blk = blockIdx.x;
    int bc  = blk >> 5;
    int m0  = (blk & 31) * 32;
    int b = bc >> 3, g = bc & 7;
    int tid = threadIdx.x;

#pragma unroll
    for (int it = 0; it < 16; it++) {
        int idx = tid + it * 256;
        int row = idx >> 5, d = idx & 31;
        const float* w = (row < 64) ? wk : wv;
        sW[row][d] = w[(size_t)(g * 64 + (row & 63)) * 32 + d];
    }
    {
        const float* qb = g_q + (size_t)b * N_ * INNER_ + g * 64;
#pragma unroll
        for (int it = 0; it < 33; it++) {
            int idx = tid + it * 256;
            if (idx < 130 * 64) {
                int i = idx >> 6, ch = idx & 63;
                int gr = 4 * m0 - 1 + i;
                sQ[i][ch] = (gr >= 0 && gr < N_) ? qb[(size_t)gr * INNER_ + ch] : 0.f;
            }
        }
    }
    __syncthreads();

    {
        int p  = tid >> 3;
        int cg = tid & 7;
        float val = 0.f;
#pragma unroll
        for (int j = 0; j < 8; j++) {
            int c = cg * 8 + j;
            float h = b1[c];
#pragma unroll
            for (int k = 0; k < KS_; k++)
                h = fmaf(sQ[4 * p + k][c], w1[c * KS_ + k], h);
            float ge = 0.5f * h * (1.f + erff(h * 0.70710678118654752f));
            val = fmaf(ge, w2[c], val);
        }
        val += __shfl_xor_sync(0xffffffffu, val, 1);
        val += __shfl_xor_sync(0xffffffffu, val, 2);
        val += __shfl_xor_sync(0xffffffffu, val, 4);
        if (cg == 0) {
            float off = tanhf(val) * 4.0f;
            sPos[p] = ((float)(m0 + p) + off) * ((float)N_ / (float)(M_ - 1)) - 0.5f;
        }
    }
    __syncthreads();

#pragma unroll
    for (int it = 0; it < 4; it++) {
        int idx = tid + it * 256;
        int m = idx & 31, ch = idx >> 5;
        float pos = sPos[m];
        float fp  = floorf(pos);
        int   i0  = (int)fp;
        float w1f = pos - fp;
        const float* base = px + (size_t)b * N_ * D_ + g * 32 + ch;
        float v0 = (i0 >= 0     && i0     < N_) ? base[(size_t)i0 * D_]       : 0.f;
        float v1 = (i0 + 1 >= 0 && i0 + 1 < N_) ? base[(size_t)(i0 + 1) * D_] : 0.f;
        skv[ch][m] = v0 * (1.f - w1f) + v1 * w1f;
    }
    __syncthreads();

#pragma unroll
    for (int u = 0; u < 8; u++) {
        int idx = tid + u * 256;
        int o = idx & 63, msub = idx >> 6;
        float acc = 0.f;
#pragma unroll
        for (int d = 0; d < 32; d++) acc = fmaf(skv[d][msub], sW[o][d], acc);
        g_kh[((size_t)b * M_ + m0 + msub) * INNER_ + g * 64 + o] = __float2half_rn(acc);
    }
#pragma unroll
    for (int u = 0; u < 8; u++) {
        int idx = tid + u * 256;
        int m = idx & 31, o = idx >> 5;
        float acc = 0.f;
#pragma unroll
        for (int d = 0; d < 32; d++) acc = fmaf(skv[d][m], sW[64 + o][d], acc);
        g_vth[((size_t)(b * 8 + g) * 64 + o) * M_ + m0 + m] = __float2half_rn(acc);
    }
}

// ---------------- K4: flash attention (BQ=128, 4 warps, 3 CTAs) ----------------
#define ATTN_SMEM ((128 * 36 + 4 * 64 * 36 + 128 * 36) * 4)
__global__ void __launch_bounds__(128, 3) k_attn() {
    int blk = blockIdx.x;
    int qt = blk & 31;
    int h  = (blk >> 5) & 7;
    int b  = blk >> 8;
    int n0 = qt << 7;

    extern __shared__ uint32_t smem[];
    uint32_t* sQ  = smem;
    uint32_t* sK  = smem + 128 * 36;
    uint32_t* sVt = smem + 128 * 36 + 2 * 64 * 36;
    uint32_t* sP  = smem + 128 * 36 + 4 * 64 * 36;

    int tid  = threadIdx.x;
    int wid  = tid >> 5, lane = tid & 31;
    int qb   = wid * 32;

    const __half* qsrc   = g_qh  + ((size_t)b * N_ + n0) * INNER_ + h * 64;
    const __half* kbase  = g_kh  + ((size_t)b * M_) * INNER_ + h * 64;
    const __half* vtbase = g_vth + ((size_t)(b * 8 + h) * 64) * M_;

#pragma unroll
    for (int it = 0; it < 8; it++) {
        int idx = tid + it * 128;
        int rr = idx >> 3, c = idx & 7;
        *(uint4*)&sQ[rr * 36 + c * 4] = *(const uint4*)(qsrc + (size_t)rr * INNER_ + c * 8);
    }

    int arow = lane & 15;
    int acol = (lane & 16) >> 2;
    int brow = (lane & 7) | ((lane >> 1) & 8);
    int bcol = (lane & 8) >> 1;
    uint32_t aQ  = cvta_smem(sQ)  + (uint32_t)(((qb + arow) * 36 + acol) * 4);
    uint32_t aP  = cvta_smem(sP)  + (uint32_t)(((qb + arow) * 36 + acol) * 4);
    uint32_t stP = aP;
    uint32_t bK  = cvta_smem(sK)  + (uint32_t)((brow * 36 + bcol) * 4);
    uint32_t bV  = cvta_smem(sVt) + (uint32_t)((brow * 36 + bcol) * 4);

    uint32_t sKaddr = cvta_smem(sK);
    uint32_t sVaddr = cvta_smem(sVt);
    auto load_tile = [&](int kt, int buf) {
        int m0 = kt << 6;
#pragma unroll
        for (int it = 0; it < 4; it++) {
            int idx = tid + it * 128;
            int rr = idx >> 3, c = idx & 7;
            CP_A16(sKaddr + (uint32_t)(buf * 64 * 36 + rr * 36 + c * 4) * 4,
                   kbase + (size_t)(m0 + rr) * INNER_ + c * 8);
        }
#pragma unroll
        for (int it = 0; it < 4; it++) {
            int idx = tid + it * 128;
            int rr = idx >> 3, c = idx & 7;
            CP_A16(sVaddr + (uint32_t)(buf * 64 * 36 + rr * 36 + c * 4) * 4,
                   vtbase + (size_t)rr * M_ + m0 + c * 8);
        }
    };

    float out[2][8][4];
#pragma unroll
    for (int u = 0; u < 2; u++)
#pragma unroll
        for (int nt = 0; nt < 8; nt++)
#pragma unroll
            for (int c = 0; c < 4; c++) out[u][nt][c] = 0.f;
    float rmax[2][2], rsum[2][2];
#pragma unroll
    for (int u = 0; u < 2; u++) { rmax[u][0] = rmax[u][1] = -1e30f; rsum[u][0] = rsum[u][1] = 0.f; }

    load_tile(0, 0);
    asm volatile("cp.async.commit_group;");

    for (int kt = 0; kt < 16; kt++) {
        int buf = kt & 1;
        if (kt < 15) {
            load_tile(kt + 1, buf ^ 1);
            asm volatile("cp.async.commit_group;");
            asm volatile("cp.async.wait_group 1;");
        } else {
            asm volatile("cp.async.wait_group 0;");
        }
        __syncthreads();

        uint32_t bufoff = (uint32_t)(buf * 64 * 36 * 4);

        float s[2][8][4];
#pragma unroll
        for (int u = 0; u < 2; u++)
#pragma unroll
            for (int nt = 0; nt < 8; nt++)
#pragma unroll
                for (int c = 0; c < 4; c++) s[u][nt][c] = 0.f;

#pragma unroll
        for (int ks = 0; ks < 4; ks++) {
            uint32_t a[2][4];
            ldm_x4(a[0][0], a[0][1], a[0][2], a[0][3], aQ + ks * 32);
            ldm_x4(a[1][0], a[1][1], a[1][2], a[1][3], aQ + 2304 + ks * 32);
#pragma unroll
            for (int ntp = 0; ntp < 4; ntp++) {
                uint32_t b00, b01, b10, b11;
                ldm_x4(b00, b01, b10, b11, bK + bufoff + ntp * 2304 + ks * 32);
                mma_f16(s[0][2 * ntp    ], a[0][0], a[0][1], a[0][2], a[0][3], b00, b01);
                mma_f16(s[1][2 * ntp    ], a[1][0], a[1][1], a[1][2], a[1][3], b00, b01);
                mma_f16(s[0][2 * ntp + 1], a[0][0], a[0][1], a[0][2], a[0][3], b10, b11);
                mma_f16(s[1][2 * ntp + 1], a[1][0], a[1][1], a[1][2], a[1][3], b10, b11);
            }
        }

#pragma unroll
        for (int u = 0; u < 2; u++) {
            float lm0 = -1e30f, lm1 = -1e30f;
#pragma unroll
            for (int nt = 0; nt < 8; nt++) {
                lm0 = fmaxf(lm0, fmaxf(s[u][nt][0], s[u][nt][1]));
                lm1 = fmaxf(lm1, fmaxf(s[u][nt][2], s[u][nt][3]));
            }
            lm0 = fmaxf(lm0, __shfl_xor_sync(0xffffffffu, lm0, 1));
            lm0 = fmaxf(lm0, __shfl_xor_sync(0xffffffffu, lm0, 2));
            lm1 = fmaxf(lm1, __shfl_xor_sync(0xffffffffu, lm1, 1));
            lm1 = fmaxf(lm1, __shfl_xor_sync(0xffffffffu, lm1, 2));
            float nm0 = fmaxf(rmax[u][0], lm0), nm1 = fmaxf(rmax[u][1], lm1);
            float f0 = exp2f(rmax[u][0] - nm0), f1 = exp2f(rmax[u][1] - nm1);
            rmax[u][0] = nm0; rmax[u][1] = nm1;
            float ls0 = 0.f, ls1 = 0.f;
#pragma unroll
            for (int ntp = 0; ntp < 4; ntp++) {
                float pa0 = exp2f(s[u][2*ntp][0] - nm0);
                float pa1 = exp2f(s[u][2*ntp][1] - nm0);
                float pa2 = exp2f(s[u][2*ntp][2] - nm1);
                float pa3 = exp2f(s[u][2*ntp][3] - nm1);
                float pb0 = exp2f(s[u][2*ntp+1][0] - nm0);
                float pb1 = exp2f(s[u][2*ntp+1][1] - nm0);
                float pb2 = exp2f(s[u][2*ntp+1][2] - nm1);
                float pb3 = exp2f(s[u][2*ntp+1][3] - nm1);
                ls0 += pa0 + pa1 + pb0 + pb1;
                ls1 += pa2 + pa3 + pb2 + pb3;
                uint32_t q0 = pack_h2(pa0, pa1);
                uint32_t q1 = pack_h2(pa2, pa3);
                uint32_t q2 = pack_h2(pb0, pb1);
                uint32_t q3 = pack_h2(pb2, pb3);
                stm_x4(stP + (uint32_t)(u * 2304 + ntp * 32), q0, q1, q2, q3);
            }
            ls0 += __shfl_xor_sync(0xffffffffu, ls0, 1);
            ls0 += __shfl_xor_sync(0xffffffffu, ls0, 2);
            ls1 += __shfl_xor_sync(0xffffffffu, ls1, 1);
            ls1 += __shfl_xor_sync(0xffffffffu, ls1, 2);
            rsum[u][0] = rsum[u][0] * f0 + ls0;
            rsum[u][1] = rsum[u][1] * f1 + ls1;
#pragma unroll
            for (int nt = 0; nt < 8; nt++) {
                out[u][nt][0] *= f0; out[u][nt][1] *= f0;
                out[u][nt][2] *= f1; out[u][nt][3] *= f1;
            }
        }
        __syncwarp();

#pragma unroll
        for (int ks = 0; ks < 4; ks++) {
            uint32_t a[2][4];
            ldm_x4(a[0][0], a[0][1], a[0][2], a[0][3], aP + ks * 32);
            ldm_x4(a[1][0], a[1][1], a[1][2], a[1][3], aP + 2304 + ks * 32);
#pragma unroll
            for (int ntp = 0; ntp < 4; ntp++) {
                uint32_t b00, b01, b10, b11;
                ldm_x4(b00, b01, b10, b11, bV + bufoff + ntp * 2304 + ks * 32);
                mma_f16(out[0][2 * ntp    ], a[0][0], a[0][1], a[0][2], a[0][3], b00, b01);
                mma_f16(out[1][2 * ntp    ], a[1][0], a[1][1], a[1][2], a[1][3], b00, b01);
                mma_f16(out[0][2 * ntp + 1], a[0][0], a[0][1], a[0][2], a[0][3], b10, b11);
                mma_f16(out[1][2 * ntp + 1], a[1][0], a[1][1], a[1][2], a[1][3], b10, b11);
            }
        }
        __syncthreads();
    }

    int r = lane >> 2, t = lane & 3;
    __half* dsth = g_aoh + ((size_t)b * N_ + n0) * INNER_ + h * 64;
#pragma unroll
    for (int u = 0; u < 2; u++) {
        int rb = qb + u * 16;
        float inv0 = 1.f / rsum[u][0], inv1 = 1.f / rsum[u][1];
#pragma unroll
        for (int nt = 0; nt < 8; nt++) {
            int col = nt * 8 + 2 * t;
            uint32_t p0 = pack_h2(out[u][nt][0] * inv0, out[u][nt][1] * inv0);
            uint32_t p1 = pack_h2(out[u][nt][2] * inv1, out[u][nt][3] * inv1);
            *(uint32_t*)(dsth + (size_t)(rb + r    ) * INNER_ + col) = p0;
            *(uint32_t*)(dsth + (size_t)(rb + r + 8) * INNER_ + col) = p1;
        }
    }
}

// ---------------- K5: output projection, fp16 mma + ldmatrix, 4 CTAs/SM ----------------
#define OPROJ_SMEM ((128 * 36 + 64 * 36) * 4)
__global__ void __launch_bounds__(256, 4) k_oproj(const float* __restrict__ wo,
                                                  const float* __restrict__ bo,
                                                  float* __restrict__ out) {
    extern __shared__ uint32_t smem[];
    uint32_t* sA = smem;
    uint32_t* sW = smem + 128 * 36;
    int row0 = blockIdx.x * 128;
    int o0   = blockIdx.y * 64;
    int tid  = threadIdx.x;
    int wid  = tid >> 5, lane = tid & 31;
    int r    = lane >> 2, t = lane & 3;
    int qb   = wid * 16;

    int arow = lane & 15;
    int acol = (lane & 16) >> 2;
    int brow = (lane & 7) | ((lane >> 1) & 8);
    int bcol = (lane & 8) >> 1;
    uint32_t aA = cvta_smem(sA) + (uint32_t)(((qb + arow) * 36 + acol) * 4);
    uint32_t bW = cvta_smem(sW) + (uint32_t)((brow * 36 + bcol) * 4);

    float s[8][4];
#pragma unroll
    for (int nt = 0; nt < 8; nt++)
#pragma unroll
        for (int c = 0; c < 4; c++) s[nt][c] = 0.f;

    for (int c0 = 0; c0 < INNER_; c0 += 64) {
#pragma unroll
        for (int it = 0; it < 4; it++) {
            int idx = tid + it * 256;
            int rr = idx >> 3, c = idx & 7;
            *(uint4*)&sA[rr * 36 + c * 4] =
                *(const uint4*)(g_aoh + (size_t)(row0 + rr) * INNER_ + c0 + c * 8);
        }
#pragma unroll
        for (int it = 0; it < 4; it++) {
            int idx = tid + it * 256;
            int rr = idx >> 4, c = idx & 15;
            float4 w4 = *(const float4*)&wo[(size_t)(o0 + rr) * INNER_ + c0 + c * 4];
            sW[rr * 36 + c * 2    ] = pack_h2(w4.x, w4.y);
            sW[rr * 36 + c * 2 + 1] = pack_h2(w4.z, w4.w);
        }
        __syncthreads();
#pragma unroll
        for (int ks = 0; ks < 4; ks++) {
            uint32_t a0, a1, a2, a3;
            ldm_x4(a0, a1, a2, a3, aA + ks * 32);
#pragma unroll
            for (int ntp = 0; ntp < 4; ntp++) {
                uint32_t b00, b01, b10, b11;
                ldm_x4(b00, b01, b10, b11, bW + ntp * 2304 + ks * 32);
                mma_f16(s[2 * ntp    ], a0, a1, a2, a3, b00, b01);
                mma_f16(s[2 * ntp + 1], a0, a1, a2, a3, b10, b11);
            }
        }
        __syncthreads();
    }

#pragma unroll
    for (int nt = 0; nt < 8; nt++) {
        int col = nt * 8 + 2 * t;
        int o = o0 + col;
        float b0 = bo[o], b1 = bo[o + 1];
        *(float2*)&out[(size_t)(row0 + qb + r    ) * D_ + o] =
            make_float2(s[nt][0] + b0, s[nt][1] + b1);
        *(float2*)&out[(size_t)(row0 + qb + r + 8) * D_ + o] =
            make_float2(s[nt][2] + b0, s[nt][3] + b1);
    }
}

// ---------------- launch ----------------
extern "C" void kernel_launch(void* const* d_in, const int* in_sizes, int n_in,
                              void* d_out, int out_size) {
    const float* x      = (const float*)d_in[0];
    const float* prev_x = (const float*)d_in[1];
    const float* wq     = (const float*)d_in[2];
    const float* wk     = (const float*)d_in[3];
    const float* wv     = (const float*)d_in[4];
    const float* wo     = (const float*)d_in[5];
    const float* bo     = (const float*)d_in[6];
    const float* w_off1 = (const float*)d_in[7];
    const float* b_off1 = (const float*)d_in[8];
    const float* w_off2 = (const float*)d_in[9];
    float* out = (float*)d_out;

    cudaFuncSetAttribute(k_attn,  cudaFuncAttributeMaxDynamicSharedMemorySize, ATTN_SMEM);
    cudaFuncSetAttribute(k_oproj, cudaFuncAttributeMaxDynamicSharedMemorySize, OPROJ_SMEM);
    cudaFuncSetAttribute(k_offkv, cudaFuncAttributeMaxDynamicSharedMemorySize, OFFKV_SMEM);

    k_qproj <<<dim3(B_ * N_ / 64, G_), 256>>>(x, prev_x, wq);
    k_offkv <<<(B_ * G_ * M_) / 32, 256, OFFKV_SMEM>>>(prev_x, wk, wv, w_off1, b_off1, w_off2);
    k_attn  <<<B_ * H_ * (N_ / 128), 128, ATTN_SMEM>>>();
    k_oproj <<<dim3((B_ * N_) / 128, D_ / 64), 256, OPROJ_SMEM>>>(wo, bo, out);
}

// round 17
// speedup vs baseline: 1.2614x; 1.0111x over previous
#include <cuda_runtime.h>
#include <cuda_fp16.h>
#include <math.h>
#include <stdint.h>

// ---------------- constants ----------------
#define B_   4
#define N_   4096
#define D_   256
#define H_   8
#define G_   8
#define DH_  64
#define INNER_ 512
#define M_   1024
#define KS_  6
#define QSCALE 0.1803368801111f   // 0.125 * log2(e)

// ---------------- helpers ----------------
__device__ __forceinline__ void mma_f16(float* d,
                                        uint32_t a0, uint32_t a1, uint32_t a2, uint32_t a3,
                                        uint32_t b0, uint32_t b1) {
    asm("mma.sync.aligned.m16n8k16.row.col.f32.f16.f16.f32 "
        "{%0,%1,%2,%3}, {%4,%5,%6,%7}, {%8,%9}, {%0,%1,%2,%3};"
        : "+f"(d[0]), "+f"(d[1]), "+f"(d[2]), "+f"(d[3])
        : "r"(a0), "r"(a1), "r"(a2), "r"(a3), "r"(b0), "r"(b1));
}
__device__ __forceinline__ void ldm_x4(uint32_t& r0, uint32_t& r1, uint32_t& r2, uint32_t& r3,
                                       uint32_t addr) {
    asm volatile("ldmatrix.sync.aligned.m8n8.x4.shared.b16 {%0,%1,%2,%3}, [%4];"
                 : "=r"(r0), "=r"(r1), "=r"(r2), "=r"(r3) : "r"(addr));
}
__device__ __forceinline__ void stm_x4(uint32_t addr, uint32_t r0, uint32_t r1,
                                       uint32_t r2, uint32_t r3) {
    asm volatile("stmatrix.sync.aligned.m8n8.x4.shared.b16 [%0], {%1,%2,%3,%4};"
                 :: "r"(addr), "r"(r0), "r"(r1), "r"(r2), "r"(r3));
}
__device__ __forceinline__ uint32_t pack_h2(float lo, float hi) {
    uint32_t r;
    asm("cvt.rn.f16x2.f32 %0, %1, %2;" : "=r"(r) : "f"(hi), "f"(lo));
    return r;
}
__device__ __forceinline__ uint32_t cvta_smem(const void* p) {
    return (uint32_t)__cvta_generic_to_shared(p);
}
#define CP_A16(dst_u32, src_ptr) \
    asm volatile("cp.async.cg.shared.global [%0], [%1], 16;" :: "r"(dst_u32), "l"(src_ptr))

// ---------------- scratch ----------------
__device__ float  g_q  [B_ * N_ * INNER_];
__device__ __half g_kh [B_ * M_ * INNER_];
__device__ __half g_vth[B_ * H_ * DH_ * M_];
__device__ __half g_aoh[B_ * N_ * INNER_];
__device__ __half g_woh[D_ * INNER_];

// ---------------- K0: convert wo -> half ----------------
__global__ __launch_bounds__(256) void k_wcvt(const float* __restrict__ wo) {
    int idx = blockIdx.x * 256 + threadIdx.x;       // 32768 float4 chunks
    float4 w4 = *(const float4*)&wo[(size_t)idx * 4];
    uint32_t* dst = (uint32_t*)(g_woh + (size_t)idx * 4);
    dst[0] = pack_h2(w4.x, w4.y);
    dst[1] = pack_h2(w4.z, w4.w);
}

// ---------------- K1: q = grouped conv1x1 (fp32, precision-critical) ----------------
__global__ __launch_bounds__(256) void k_qproj(const float* __restrict__ x,
                                               const float* __restrict__ px,
                                               const float* __restrict__ wq) {
    __shared__ float sIn[64][68];
    __shared__ float sW [64][68];
    int tok0 = blockIdx.x * 64;
    int g    = blockIdx.y;
    int tid  = threadIdx.x;
    int ty = tid >> 4, tx = tid & 15;

    const float* src = (g < 4) ? px : x;
    int cb = (g & 3) * 64;

#pragma unroll
    for (int it = 0; it < 4; it++) {
        int idx = tid + it * 256;
        int r = idx >> 4, c4 = (idx & 15) * 4;
        *(float4*)&sIn[r][c4] = *(const float4*)&src[(size_t)(tok0 + r) * D_ + cb + c4];
        *(float4*)&sW [r][c4] = *(const float4*)&wq [(size_t)(g * 64 + r) * 64 + c4];
    }
    __syncthreads();

    float acc[4][4];
#pragma unroll
    for (int i = 0; i < 4; i++)
#pragma unroll
        for (int j = 0; j < 4; j++) acc[i][j] = 0.f;

#pragma unroll
    for (int d0 = 0; d0 < 64; d0 += 4) {
        float4 av[4], wv[4];
#pragma unroll
        for (int i = 0; i < 4; i++) av[i] = *(const float4*)&sIn[ty + 16 * i][d0];
#pragma unroll
        for (int j = 0; j < 4; j++) wv[j] = *(const float4*)&sW[tx + 16 * j][d0];
#pragma unroll
        for (int i = 0; i < 4; i++)
#pragma unroll
            for (int j = 0; j < 4; j++) {
                acc[i][j] = fmaf(av[i].x, wv[j].x, acc[i][j]);
                acc[i][j] = fmaf(av[i].y, wv[j].y, acc[i][j]);
                acc[i][j] = fmaf(av[i].z, wv[j].z, acc[i][j]);
                acc[i][j] = fmaf(av[i].w, wv[j].w, acc[i][j]);
            }
    }
#pragma unroll
    for (int i = 0; i < 4; i++)
#pragma unroll
        for (int j = 0; j < 4; j++)
            g_q[(size_t)(tok0 + ty + 16 * i) * INNER_ + g * 64 + tx + 16 * j] = acc[i][j];
}

// ---------------- K2: fused offsets + gather + k/v conv1x1 ----------------
#define OFFKV_SMEM ((130 * 65 + 128 * 33 + 32 * 33 + 32) * 4)
__global__ __launch_bounds__(256) void k_offkv(const float* __restrict__ px,
                                               const float* __restrict__ wk,
                                               const float* __restrict__ wv,
                                               const float* __restrict__ w1,
                                               const float* __restrict__ b1,
                                               const float* __restrict__ w2) {
    extern __shared__ float sm[];
    float (*sQ) [65] = (float(*)[65])sm;
    float (*sW) [33] = (float(*)[33])(sm + 130 * 65);
    float (*skv)[33] = (float(*)[33])(sm + 130 * 65 + 128 * 33);
    float* sPos      = sm + 130 * 65 + 128 * 33 + 32 * 33;

    int blk = blockIdx.x;
    int bc  = blk >> 5;
    int m0  = (blk & 31) * 32;
    int b = bc >> 3, g = bc & 7;
    int tid = threadIdx.x;

#pragma unroll
    for (int it = 0; it < 16; it++) {
        int idx = tid + it * 256;
        int row = idx >> 5, d = idx & 31;
        const float* w = (row < 64) ? wk : wv;
        sW[row][d] = w[(size_t)(g * 64 + (row & 63)) * 32 + d];
    }
    {
        const float* qb = g_q + (size_t)b * N_ * INNER_ + g * 64;
#pragma unroll
        for (int it = 0; it < 33; it++) {
            int idx = tid + it * 256;
            if (idx < 130 * 64) {
                int i = idx >> 6, ch = idx & 63;
                int gr = 4 * m0 - 1 + i;
                sQ[i][ch] = (gr >= 0 && gr < N_) ? qb[(size_t)gr * INNER_ + ch] : 0.f;
            }
        }
    }
    __syncthreads();

    {
        int p  = tid >> 3;
        int cg = tid & 7;
        float val = 0.f;
#pragma unroll
        for (int j = 0; j < 8; j++) {
            int c = cg * 8 + j;
            float h = b1[c];
#pragma unroll
            for (int k = 0; k < KS_; k++)
                h = fmaf(sQ[4 * p + k][c], w1[c * KS_ + k], h);
            float ge = 0.5f * h * (1.f + erff(h * 0.70710678118654752f));
            val = fmaf(ge, w2[c], val);
        }
        val += __shfl_xor_sync(0xffffffffu, val, 1);
        val += __shfl_xor_sync(0xffffffffu, val, 2);
        val += __shfl_xor_sync(0xffffffffu, val, 4);
        if (cg == 0) {
            float off = tanhf(val) * 4.0f;
            sPos[p] = ((float)(m0 + p) + off) * ((float)N_ / (float)(M_ - 1)) - 0.5f;
        }
    }
    __syncthreads();

#pragma unroll
    for (int it = 0; it < 4; it++) {
        int idx = tid + it * 256;
        int m = idx & 31, ch = idx >> 5;
        float pos = sPos[m];
        float fp  = floorf(pos);
        int   i0  = (int)fp;
        float w1f = pos - fp;
        const float* base = px + (size_t)b * N_ * D_ + g * 32 + ch;
        float v0 = (i0 >= 0     && i0     < N_) ? base[(size_t)i0 * D_]       : 0.f;
        float v1 = (i0 + 1 >= 0 && i0 + 1 < N_) ? base[(size_t)(i0 + 1) * D_] : 0.f;
        skv[ch][m] = v0 * (1.f - w1f) + v1 * w1f;
    }
    __syncthreads();

#pragma unroll
    for (int u = 0; u < 8; u++) {
        int idx = tid + u * 256;
        int o = idx & 63, msub = idx >> 6;
        float acc = 0.f;
#pragma unroll
        for (int d = 0; d < 32; d++) acc = fmaf(skv[d][msub], sW[o][d], acc);
        g_kh[((size_t)b * M_ + m0 + msub) * INNER_ + g * 64 + o] = __float2half_rn(acc);
    }
#pragma unroll
    for (int u = 0; u < 8; u++) {
        int idx = tid + u * 256;
        int m = idx & 31, o = idx >> 5;
        float acc = 0.f;
#pragma unroll
        for (int d = 0; d < 32; d++) acc = fmaf(skv[d][m], sW[64 + o][d], acc);
        g_vth[((size_t)(b * 8 + g) * 64 + o) * M_ + m0 + m] = __float2half_rn(acc);
    }
}

// ---------------- K4: flash attention (BQ=128, 4 warps, 3 CTAs) ----------------
#define ATTN_SMEM ((128 * 36 + 4 * 64 * 36 + 128 * 36) * 4)
__global__ void __launch_bounds__(128, 3) k_attn() {
    int blk = blockIdx.x;
    int qt = blk & 31;
    int h  = (blk >> 5) & 7;
    int b  = blk >> 8;
    int n0 = qt << 7;

    extern __shared__ uint32_t smem[];
    uint32_t* sQ  = smem;
    uint32_t* sK  = smem + 128 * 36;
    uint32_t* sVt = smem + 128 * 36 + 2 * 64 * 36;
    uint32_t* sP  = smem + 128 * 36 + 4 * 64 * 36;

    int tid  = threadIdx.x;
    int wid  = tid >> 5, lane = tid & 31;
    int qb   = wid * 32;

    const float*  qsrc   = g_q   + ((size_t)b * N_ + n0) * INNER_ + h * 64;
    const __half* kbase  = g_kh  + ((size_t)b * M_) * INNER_ + h * 64;
    const __half* vtbase = g_vth + ((size_t)(b * 8 + h) * 64) * M_;

    // ---- stage Q (fp32 -> fp16, scaled): 128 rows x 16 float4 ----
#pragma unroll
    for (int it = 0; it < 16; it++) {
        int idx = tid + it * 128;
        int rr = idx >> 4, c = idx & 15;
        float4 q4 = *(const float4*)&qsrc[(size_t)rr * INNER_ + c * 4];
        sQ[rr * 36 + c * 2    ] = pack_h2(q4.x * QSCALE, q4.y * QSCALE);
        sQ[rr * 36 + c * 2 + 1] = pack_h2(q4.z * QSCALE, q4.w * QSCALE);
    }

    int arow = lane & 15;
    int acol = (lane & 16) >> 2;
    int brow = (lane & 7) | ((lane >> 1) & 8);
    int bcol = (lane & 8) >> 1;
    uint32_t aQ  = cvta_smem(sQ)  + (uint32_t)(((qb + arow) * 36 + acol) * 4);
    uint32_t aP  = cvta_smem(sP)  + (uint32_t)(((qb + arow) * 36 + acol) * 4);
    uint32_t stP = aP;
    uint32_t bK  = cvta_smem(sK)  + (uint32_t)((brow * 36 + bcol) * 4);
    uint32_t bV  = cvta_smem(sVt) + (uint32_t)((brow * 36 + bcol) * 4);

    uint32_t sKaddr = cvta_smem(sK);
    uint32_t sVaddr = cvta_smem(sVt);
    auto load_tile = [&](int kt, int buf) {
        int m0 = kt << 6;
#pragma unroll
        for (int it = 0; it < 4; it++) {
            int idx = tid + it * 128;
            int rr = idx >> 3, c = idx & 7;
            CP_A16(sKaddr + (uint32_t)(buf * 64 * 36 + rr * 36 + c * 4) * 4,
                   kbase + (size_t)(m0 + rr) * INNER_ + c * 8);
        }
#pragma unroll
        for (int it = 0; it < 4; it++) {
            int idx = tid + it * 128;
            int rr = idx >> 3, c = idx & 7;
            CP_A16(sVaddr + (uint32_t)(buf * 64 * 36 + rr * 36 + c * 4) * 4,
                   vtbase + (size_t)rr * M_ + m0 + c * 8);
        }
    };

    float out[2][8][4];
#pragma unroll
    for (int u = 0; u < 2; u++)
#pragma unroll
        for (int nt = 0; nt < 8; nt++)
#pragma unroll
            for (int c = 0; c < 4; c++) out[u][nt][c] = 0.f;
    float rmax[2][2], rsum[2][2];
#pragma unroll
    for (int u = 0; u < 2; u++) { rmax[u][0] = rmax[u][1] = -1e30f; rsum[u][0] = rsum[u][1] = 0.f; }

    load_tile(0, 0);
    asm volatile("cp.async.commit_group;");

    for (int kt = 0; kt < 16; kt++) {
        int buf = kt & 1;
        if (kt < 15) {
            load_tile(kt + 1, buf ^ 1);
            asm volatile("cp.async.commit_group;");
            asm volatile("cp.async.wait_group 1;");
        } else {
            asm volatile("cp.async.wait_group 0;");
        }
        __syncthreads();

        uint32_t bufoff = (uint32_t)(buf * 64 * 36 * 4);

        float s[2][8][4];
#pragma unroll
        for (int u = 0; u < 2; u++)
#pragma unroll
            for (int nt = 0; nt < 8; nt++)
#pragma unroll
                for (int c = 0; c < 4; c++) s[u][nt][c] = 0.f;

#pragma unroll
        for (int ks = 0; ks < 4; ks++) {
            uint32_t a[2][4];
            ldm_x4(a[0][0], a[0][1], a[0][2], a[0][3], aQ + ks * 32);
            ldm_x4(a[1][0], a[1][1], a[1][2], a[1][3], aQ + 2304 + ks * 32);
#pragma unroll
            for (int ntp = 0; ntp < 4; ntp++) {
                uint32_t b00, b01, b10, b11;
                ldm_x4(b00, b01, b10, b11, bK + bufoff + ntp * 2304 + ks * 32);
                mma_f16(s[0][2 * ntp    ], a[0][0], a[0][1], a[0][2], a[0][3], b00, b01);
                mma_f16(s[1][2 * ntp    ], a[1][0], a[1][1], a[1][2], a[1][3], b00, b01);
                mma_f16(s[0][2 * ntp + 1], a[0][0], a[0][1], a[0][2], a[0][3], b10, b11);
                mma_f16(s[1][2 * ntp + 1], a[1][0], a[1][1], a[1][2], a[1][3], b10, b11);
            }
        }

#pragma unroll
        for (int u = 0; u < 2; u++) {
            float lm0 = -1e30f, lm1 = -1e30f;
#pragma unroll
            for (int nt = 0; nt < 8; nt++) {
                lm0 = fmaxf(lm0, fmaxf(s[u][nt][0], s[u][nt][1]));
                lm1 = fmaxf(lm1, fmaxf(s[u][nt][2], s[u][nt][3]));
            }
            lm0 = fmaxf(lm0, __shfl_xor_sync(0xffffffffu, lm0, 1));
            lm0 = fmaxf(lm0, __shfl_xor_sync(0xffffffffu, lm0, 2));
            lm1 = fmaxf(lm1, __shfl_xor_sync(0xffffffffu, lm1, 1));
            lm1 = fmaxf(lm1, __shfl_xor_sync(0xffffffffu, lm1, 2));
            float nm0 = fmaxf(rmax[u][0], lm0), nm1 = fmaxf(rmax[u][1], lm1);
            float f0 = exp2f(rmax[u][0] - nm0), f1 = exp2f(rmax[u][1] - nm1);
            rmax[u][0] = nm0; rmax[u][1] = nm1;
            float ls0 = 0.f, ls1 = 0.f;
#pragma unroll
            for (int ntp = 0; ntp < 4; ntp++) {
                float pa0 = exp2f(s[u][2*ntp][0] - nm0);
                float pa1 = exp2f(s[u][2*ntp][1] - nm0);
                float pa2 = exp2f(s[u][2*ntp][2] - nm1);
                float pa3 = exp2f(s[u][2*ntp][3] - nm1);
                float pb0 = exp2f(s[u][2*ntp+1][0] - nm0);
                float pb1 = exp2f(s[u][2*ntp+1][1] - nm0);
                float pb2 = exp2f(s[u][2*ntp+1][2] - nm1);
                float pb3 = exp2f(s[u][2*ntp+1][3] - nm1);
                ls0 += pa0 + pa1 + pb0 + pb1;
                ls1 += pa2 + pa3 + pb2 + pb3;
                uint32_t q0 = pack_h2(pa0, pa1);
                uint32_t q1 = pack_h2(pa2, pa3);
                uint32_t q2 = pack_h2(pb0, pb1);
                uint32_t q3 = pack_h2(pb2, pb3);
                stm_x4(stP + (uint32_t)(u * 2304 + ntp * 32), q0, q1, q2, q3);
            }
            ls0 += __shfl_xor_sync(0xffffffffu, ls0, 1);
            ls0 += __shfl_xor_sync(0xffffffffu, ls0, 2);
            ls1 += __shfl_xor_sync(0xffffffffu, ls1, 1);
            ls1 += __shfl_xor_sync(0xffffffffu, ls1, 2);
            rsum[u][0] = rsum[u][0] * f0 + ls0;
            rsum[u][1] = rsum[u][1] * f1 + ls1;
#pragma unroll
            for (int nt = 0; nt < 8; nt++) {
                out[u][nt][0] *= f0; out[u][nt][1] *= f0;
                out[u][nt][2] *= f1; out[u][nt][3] *= f1;
            }
        }
        __syncwarp();

#pragma unroll
        for (int ks = 0; ks < 4; ks++) {
            uint32_t a[2][4];
            ldm_x4(a[0][0], a[0][1], a[0][2], a[0][3], aP + ks * 32);
            ldm_x4(a[1][0], a[1][1], a[1][2], a[1][3], aP + 2304 + ks * 32);
#pragma unroll
            for (int ntp = 0; ntp < 4; ntp++) {
                uint32_t b00, b01, b10, b11;
                ldm_x4(b00, b01, b10, b11, bV + bufoff + ntp * 2304 + ks * 32);
                mma_f16(out[0][2 * ntp    ], a[0][0], a[0][1], a[0][2], a[0][3], b00, b01);
                mma_f16(out[1][2 * ntp    ], a[1][0], a[1][1], a[1][2], a[1][3], b00, b01);
                mma_f16(out[0][2 * ntp + 1], a[0][0], a[0][1], a[0][2], a[0][3], b10, b11);
                mma_f16(out[1][2 * ntp + 1], a[1][0], a[1][1], a[1][2], a[1][3], b10, b11);
            }
        }
        __syncthreads();
    }

    int r = lane >> 2, t = lane & 3;
    __half* dsth = g_aoh + ((size_t)b * N_ + n0) * INNER_ + h * 64;
#pragma unroll
    for (int u = 0; u < 2; u++) {
        int rb = qb + u * 16;
        float inv0 = 1.f / rsum[u][0], inv1 = 1.f / rsum[u][1];
#pragma unroll
        for (int nt = 0; nt < 8; nt++) {
            int col = nt * 8 + 2 * t;
            uint32_t p0 = pack_h2(out[u][nt][0] * inv0, out[u][nt][1] * inv0);
            uint32_t p1 = pack_h2(out[u][nt][2] * inv1, out[u][nt][3] * inv1);
            *(uint32_t*)(dsth + (size_t)(rb + r    ) * INNER_ + col) = p0;
            *(uint32_t*)(dsth + (size_t)(rb + r + 8) * INNER_ + col) = p1;
        }
    }
}

// ---------------- K5: output projection, fp16 mma + cp.async double buffer ----------------
// smem u32: A 2x[128*36] | W 2x[64*36]
#define OPROJ_SMEM ((2 * 128 * 36 + 2 * 64 * 36) * 4)
__global__ void __launch_bounds__(256, 3) k_oproj(const float* __restrict__ bo,
                                                  float* __restrict__ out) {
    extern __shared__ uint32_t smem[];
    uint32_t* sA = smem;                    // 2 x 128*36
    uint32_t* sW = smem + 2 * 128 * 36;     // 2 x 64*36
    int row0 = blockIdx.x * 128;
    int o0   = blockIdx.y * 64;
    int tid  = threadIdx.x;
    int wid  = tid >> 5, lane = tid & 31;
    int r    = lane >> 2, t = lane & 3;
    int qb   = wid * 16;

    int arow = lane & 15;
    int acol = (lane & 16) >> 2;
    int brow = (lane & 7) | ((lane >> 1) & 8);
    int bcol = (lane & 8) >> 1;
    uint32_t aA = cvta_smem(sA) + (uint32_t)(((qb + arow) * 36 + acol) * 4);
    uint32_t bW = cvta_smem(sW) + (uint32_t)((brow * 36 + bcol) * 4);

    uint32_t sAaddr = cvta_smem(sA);
    uint32_t sWaddr = cvta_smem(sW);
    auto load_tile = [&](int c0, int buf) {
#pragma unroll
        for (int it = 0; it < 4; it++) {
            int idx = tid + it * 256;
            int rr = idx >> 3, c = idx & 7;
            CP_A16(sAaddr + (uint32_t)(buf * 128 * 36 + rr * 36 + c * 4) * 4,
                   g_aoh + (size_t)(row0 + rr) * INNER_ + c0 + c * 8);
        }
#pragma unroll
        for (int it = 0; it < 2; it++) {
            int idx = tid + it * 256;
            int rr = idx >> 3, c = idx & 7;
            CP_A16(sWaddr + (uint32_t)(buf * 64 * 36 + rr * 36 + c * 4) * 4,
                   g_woh + (size_t)(o0 + rr) * INNER_ + c0 + c * 8);
        }
    };

    float s[8][4];
#pragma unroll
    for (int nt = 0; nt < 8; nt++)
#pragma unroll
        for (int c = 0; c < 4; c++) s[nt][c] = 0.f;

    load_tile(0, 0);
    asm volatile("cp.async.commit_group;");

    for (int cc = 0; cc < 8; cc++) {
        int buf = cc & 1;
        if (cc < 7) {
            load_tile((cc + 1) * 64, buf ^ 1);
            asm volatile("cp.async.commit_group;");
            asm volatile("cp.async.wait_group 1;");
        } else {
            asm volatile("cp.async.wait_group 0;");
        }
        __syncthreads();

        uint32_t aoff = (uint32_t)(buf * 128 * 36 * 4);
        uint32_t woff = (uint32_t)(buf * 64 * 36 * 4);
#pragma unroll
        for (int ks = 0; ks < 4; ks++) {
            uint32_t a0, a1, a2, a3;
            ldm_x4(a0, a1, a2, a3, aA + aoff + ks * 32);
#pragma unroll
            for (int ntp = 0; ntp < 4; ntp++) {
                uint32_t b00, b01, b10, b11;
                ldm_x4(b00, b01, b10, b11, bW + woff + ntp * 2304 + ks * 32);
                mma_f16(s[2 * ntp    ], a0, a1, a2, a3, b00, b01);
                mma_f16(s[2 * ntp + 1], a0, a1, a2, a3, b10, b11);
            }
        }
        __syncthreads();
    }

#pragma unroll
    for (int nt = 0; nt < 8; nt++) {
        int col = nt * 8 + 2 * t;
        int o = o0 + col;
        float b0 = bo[o], b1 = bo[o + 1];
        *(float2*)&out[(size_t)(row0 + qb + r    ) * D_ + o] =
            make_float2(s[nt][0] + b0, s[nt][1] + b1);
        *(float2*)&out[(size_t)(row0 + qb + r + 8) * D_ + o] =
            make_float2(s[nt][2] + b0, s[nt][3] + b1);
    }
}

// ---------------- launch ----------------
extern "C" void kernel_launch(void* const* d_in, const int* in_sizes, int n_in,
                              void* d_out, int out_size) {
    const float* x      = (const float*)d_in[0];
    const float* prev_x = (const float*)d_in[1];
    const float* wq     = (const float*)d_in[2];
    const float* wk     = (const float*)d_in[3];
    const float* wv     = (const float*)d_in[4];
    const float* wo     = (const float*)d_in[5];
    const float* bo     = (const float*)d_in[6];
    const float* w_off1 = (const float*)d_in[7];
    const float* b_off1 = (const float*)d_in[8];
    const float* w_off2 = (const float*)d_in[9];
    float* out = (float*)d_out;

    cudaFuncSetAttribute(k_attn,  cudaFuncAttributeMaxDynamicSharedMemorySize, ATTN_SMEM);
    cudaFuncSetAttribute(k_oproj, cudaFuncAttributeMaxDynamicSharedMemorySize, OPROJ_SMEM);
    cudaFuncSetAttribute(k_offkv, cudaFuncAttributeMaxDynamicSharedMemorySize, OFFKV_SMEM);

    k_wcvt  <<<(D_ * INNER_ / 4) / 256, 256>>>(wo);
    k_qproj <<<dim3(B_ * N_ / 64, G_), 256>>>(x, prev_x, wq);
    k_offkv <<<(B_ * G_ * M_) / 32, 256, OFFKV_SMEM>>>(prev_x, wk, wv, w_off1, b_off1, w_off2);
    k_attn  <<<B_ * H_ * (N_ / 128), 128, ATTN_SMEM>>>();
    k_oproj <<<dim3((B_ * N_) / 128, D_ / 64), 256, OPROJ_SMEM>>>(bo, out);
}